// round 10
// baseline (speedup 1.0000x reference)
#include <cuda_runtime.h>
#include <cuda_bf16.h>
#include <math.h>
#include <stdint.h>

#define DIM 256
#define HEADS 8
#define WS 8
#define B_ 8
#define NTOK (B_*128*128)          // 131072
#define MLP_HIDDEN 1024
#define SCALE_ 0.17677669529663687f

// ---------------- scratch ----------------
__device__ float g_qkv [NTOK * 768];
__device__ float g_attn[NTOK * DIM];          // reused as rounded-x before step 2
__device__ float g_x   [NTOK * DIM];
__device__ float g_ln  [NTOK * DIM];
__device__ float g_h   [NTOK * MLP_HIDDEN];
__device__ float g_pool [B_ * 256 * DIM];
__device__ float g_qkvg [B_ * 256 * 768];
__device__ float g_attng[B_ * 256 * DIM];
__device__ float g_wr  [1048576];             // rounded weights

#define OFF_QKVW  0
#define OFF_PROJW 196608
#define OFF_PROJ2W 262144
#define OFF_FC1W  327680
#define OFF_FC2W  589824
#define OFF_QKV2W 851968

// ---------------- helpers ----------------
__device__ __forceinline__ uint32_t smem_u32(const void* p) {
    uint32_t a;
    asm("{ .reg .u64 t; cvta.to.shared.u64 t, %1; cvt.u32.u64 %0, t; }" : "=r"(a) : "l"(p));
    return a;
}
#define CP16(dst, src) \
    asm volatile("cp.async.cg.shared.global [%0], [%1], 16;" :: "r"(dst), "l"(src))
#define CP_COMMIT() asm volatile("cp.async.commit_group;" ::: "memory")
#define CP_WAIT3()  asm volatile("cp.async.wait_group 3;" ::: "memory")

__device__ __forceinline__ uint32_t f2tf32(float f) {
    uint32_t u;
    asm("cvt.rna.tf32.f32 %0, %1;" : "=r"(u) : "f"(f));
    return u;
}
__device__ __forceinline__ float rnd_tf32(float f) {
    return __uint_as_float(f2tf32(f));
}
__device__ __forceinline__ void mma_tf32(float* d, float a0, float a1, float a2, float a3,
                                         float b0, float b1) {
    asm volatile(
        "mma.sync.aligned.m16n8k8.row.col.f32.tf32.tf32.f32 "
        "{%0,%1,%2,%3}, {%4,%5,%6,%7}, {%8,%9}, {%0,%1,%2,%3};"
        : "+f"(d[0]), "+f"(d[1]), "+f"(d[2]), "+f"(d[3])
        : "r"(__float_as_uint(a0)), "r"(__float_as_uint(a1)),
          "r"(__float_as_uint(a2)), "r"(__float_as_uint(a3)),
          "r"(__float_as_uint(b0)), "r"(__float_as_uint(b1)));
}

// ---------------- tf32 round kernel ----------------
__global__ __launch_bounds__(256)
void round4_k(const float4* __restrict__ in, float4* __restrict__ out, int n4)
{
    int i = blockIdx.x * 256 + threadIdx.x;
    if (i < n4) {
        float4 v = in[i];
        v.x = rnd_tf32(v.x); v.y = rnd_tf32(v.y);
        v.z = rnd_tf32(v.z); v.w = rnd_tf32(v.w);
        out[i] = v;
    }
}

// ---------------- tf32 mma.sync GEMM (R5 tile, 5-stage pipeline, swapped grid) --
// C[M,N] = A[M,K] @ B[N,K]^T + bias (+epi); A,B pre-rounded to tf32
// grid: x = n-block (fastest -> A-tile L2 reuse), y = m-block
// EPI: 0 none, 1 +res, 2 gelu(exact, rounded output)
#define BM 128
#define BN 128
#define BK 32
#define STG 5
#define APAD 36
#define ASZ (BM*APAD)
#define BSZ (BN*APAD)
#define STAGE_F (ASZ + BSZ)
#define MGEMM_SMEM (STG * STAGE_F * 4)   // 184320 B (1 CTA/SM)

__device__ __forceinline__ void load_tile(const float* __restrict__ Ag,
                                          const float* __restrict__ Bg,
                                          int K, uint32_t sA, uint32_t sB, int t)
{
#pragma unroll
    for (int i = 0; i < 4; i++) {
        int idx = i * 256 + t;
        int row = idx >> 3, ch = idx & 7;
        CP16(sA + row * (APAD * 4) + ch * 16, Ag + (size_t)row * K + ch * 4);
    }
#pragma unroll
    for (int i = 0; i < 4; i++) {
        int idx = i * 256 + t;
        int row = idx >> 3, ch = idx & 7;
        CP16(sB + row * (APAD * 4) + ch * 16, Bg + (size_t)row * K + ch * 4);
    }
}

template<int EPI>
__global__ __launch_bounds__(256)
void mgemm_k(const float* __restrict__ A, const float* __restrict__ Bw,
             const float* __restrict__ bias, const float* __restrict__ res,
             float* __restrict__ C, int M, int N, int K)
{
    extern __shared__ float sm[];
    const uint32_t smb = smem_u32(sm);

    const int t = threadIdx.x, lane = t & 31, warp = t >> 5;
    const int wm = warp >> 1, wn = warp & 1;
    const int bm = blockIdx.y * BM, bn = blockIdx.x * BN;   // n fastest
    const int nk = K / BK;
    const int r = lane >> 2, cq = lane & 3;

    float acc[2][8][4];
#pragma unroll
    for (int i = 0; i < 2; i++)
#pragma unroll
        for (int j = 0; j < 8; j++)
#pragma unroll
            for (int q = 0; q < 4; q++) acc[i][j][q] = 0.f;

    const float* Abase = A + (size_t)bm * K;
    const float* Bbase = Bw + (size_t)bn * K;

#pragma unroll
    for (int s = 0; s < STG - 1; s++) {
        load_tile(Abase + s * BK, Bbase + s * BK, K,
                  smb + s * STAGE_F * 4, smb + (s * STAGE_F + ASZ) * 4, t);
        CP_COMMIT();
    }

    for (int kt = 0; kt < nk; kt++) {
        CP_WAIT3();
        __syncthreads();
        const int pf = kt + STG - 1;
        if (pf < nk) {
            const int st = pf % STG;
            load_tile(Abase + pf * BK, Bbase + pf * BK, K,
                      smb + st * STAGE_F * 4, smb + (st * STAGE_F + ASZ) * 4, t);
        }
        CP_COMMIT();

        const float* sA = sm + (kt % STG) * STAGE_F;
        const float* sB = sA + ASZ;
#pragma unroll
        for (int ks = 0; ks < 4; ks++) {
            const int k0 = ks * 8;
            float a[2][4];
#pragma unroll
            for (int mi = 0; mi < 2; mi++) {
                const int row = wm * 32 + mi * 16;
                a[mi][0] = sA[(row + r)     * APAD + k0 + cq];
                a[mi][1] = sA[(row + r + 8) * APAD + k0 + cq];
                a[mi][2] = sA[(row + r)     * APAD + k0 + cq + 4];
                a[mi][3] = sA[(row + r + 8) * APAD + k0 + cq + 4];
            }
            float b[8][2];
#pragma unroll
            for (int ni = 0; ni < 8; ni++) {
                const int col = wn * 64 + ni * 8;
                b[ni][0] = sB[(col + r) * APAD + k0 + cq];
                b[ni][1] = sB[(col + r) * APAD + k0 + cq + 4];
            }
#pragma unroll
            for (int mi = 0; mi < 2; mi++)
#pragma unroll
                for (int ni = 0; ni < 8; ni++)
                    mma_tf32(acc[mi][ni], a[mi][0], a[mi][1], a[mi][2], a[mi][3],
                             b[ni][0], b[ni][1]);
        }
    }

    // epilogue
#pragma unroll
    for (int ni = 0; ni < 8; ni++) {
        const int col = bn + wn * 64 + ni * 8 + cq * 2;
        const float b0 = bias[col], b1 = bias[col + 1];
#pragma unroll
        for (int mi = 0; mi < 2; mi++) {
            const int row0 = bm + wm * 32 + mi * 16 + r;
#pragma unroll
            for (int h = 0; h < 2; h++) {
                const int row = row0 + h * 8;
                float2 o;
                o.x = acc[mi][ni][h * 2 + 0] + b0;
                o.y = acc[mi][ni][h * 2 + 1] + b1;
                const size_t off = (size_t)row * N + col;
                if (EPI == 1) {
                    const float2 rr = *(const float2*)(res + off);
                    o.x += rr.x; o.y += rr.y;
                }
                if (EPI == 2) {
                    o.x = rnd_tf32(0.5f * o.x * (1.f + erff(o.x * 0.70710678118654752f)));
                    o.y = rnd_tf32(0.5f * o.y * (1.f + erff(o.y * 0.70710678118654752f)));
                }
                *(float2*)(C + off) = o;
            }
        }
    }
}

// ---------------- window attention ----------------
__global__ __launch_bounds__(256)
void win_attn_k(const float* __restrict__ qkv, const float* __restrict__ rel_table,
                const int* __restrict__ rel_idx, float* __restrict__ out)
{
    const int win = blockIdx.x;
    const int h   = blockIdx.y;
    const int b   = win >> 8;
    const int wr  = (win >> 4) & 15;
    const int wc  = win & 15;

    __shared__ float q[64][33], k[64][33], v[64][33];
    __shared__ float s[64][65];

    const int t = threadIdx.x;
#pragma unroll
    for (int i = 0; i < 8; i++) {
        int e = i * 256 + t;
        int tok = e >> 5, d = e & 31;
        int ti = tok >> 3, tj = tok & 7;
        size_t row = ((size_t)(b * 128 + wr * 8 + ti) * 128 + (wc * 8 + tj));
        const float* base = qkv + row * 768 + h * 32 + d;
        q[tok][d] = base[0];
        k[tok][d] = base[256];
        v[tok][d] = base[512];
    }
    __syncthreads();

    const int qi = t >> 2;
    const int j0 = (t & 3) * 16;
#pragma unroll
    for (int j = j0; j < j0 + 16; j++) {
        float a = 0.f;
#pragma unroll
        for (int d = 0; d < 32; d++) a = fmaf(q[qi][d], k[j][d], a);
        s[qi][j] = a * SCALE_ + rel_table[rel_idx[qi * 64 + j] * HEADS + h];
    }
    __syncthreads();

    const int warp = t >> 5, lane = t & 31;
    for (int r = warp * 8; r < warp * 8 + 8; r++) {
        float a = s[r][lane], bvv = s[r][lane + 32];
        float mx = fmaxf(a, bvv);
#pragma unroll
        for (int o = 16; o; o >>= 1) mx = fmaxf(mx, __shfl_xor_sync(0xffffffffu, mx, o));
        a = __expf(a - mx); bvv = __expf(bvv - mx);
        float sum = a + bvv;
#pragma unroll
        for (int o = 16; o; o >>= 1) sum += __shfl_xor_sync(0xffffffffu, sum, o);
        float inv = 1.f / sum;
        s[r][lane] = a * inv; s[r][lane + 32] = bvv * inv;
    }
    __syncthreads();

    const int d0 = (t & 3) * 8;
    float acc[8];
#pragma unroll
    for (int dd = 0; dd < 8; dd++) acc[dd] = 0.f;
    for (int j = 0; j < 64; j++) {
        float p = s[qi][j];
#pragma unroll
        for (int dd = 0; dd < 8; dd++) acc[dd] = fmaf(p, v[j][d0 + dd], acc[dd]);
    }
    int ti = qi >> 3, tj = qi & 7;
    size_t row = ((size_t)(b * 128 + wr * 8 + ti) * 128 + (wc * 8 + tj));
    float* ob = out + row * 256 + h * 32 + d0;
#pragma unroll
    for (int dd = 0; dd < 8; dd++) ob[dd] = acc[dd];
}

// ---------------- add + LN (ln rounded) ----------------
__global__ __launch_bounds__(256)
void add_ln_k(const float* __restrict__ x, const float* __restrict__ a,
              const float* __restrict__ w, const float* __restrict__ bb,
              float* __restrict__ xo, float* __restrict__ lo)
{
    const int warp = threadIdx.x >> 5, lane = threadIdx.x & 31;
    const size_t tok = (size_t)blockIdx.x * 8 + warp;
    const float* xr = x + tok * 256;
    const float* ar = a + tok * 256;
    float v[8]; float sum = 0.f;
#pragma unroll
    for (int i = 0; i < 8; i++) { int c = i * 32 + lane; v[i] = xr[c] + ar[c]; sum += v[i]; }
#pragma unroll
    for (int o = 16; o; o >>= 1) sum += __shfl_xor_sync(0xffffffffu, sum, o);
    float mean = sum * (1.f / 256.f);
    float s2 = 0.f;
#pragma unroll
    for (int i = 0; i < 8; i++) { float d = v[i] - mean; s2 += d * d; }
#pragma unroll
    for (int o = 16; o; o >>= 1) s2 += __shfl_xor_sync(0xffffffffu, s2, o);
    float rstd = rsqrtf(s2 * (1.f / 256.f) + 1e-5f);
    float* xr2 = xo + tok * 256;
    float* lr  = lo + tok * 256;
#pragma unroll
    for (int i = 0; i < 8; i++) {
        int c = i * 32 + lane;
        xr2[c] = v[i];
        lr[c]  = rnd_tf32((v[i] - mean) * rstd * w[c] + bb[c]);
    }
}

// ---------------- LN only ----------------
template<int RND>
__global__ __launch_bounds__(256)
void ln_k(const float* __restrict__ x, const float* __restrict__ w,
          const float* __restrict__ bb, float* __restrict__ lo)
{
    const int warp = threadIdx.x >> 5, lane = threadIdx.x & 31;
    const size_t tok = (size_t)blockIdx.x * 8 + warp;
    const float* xr = x + tok * 256;
    float v[8]; float sum = 0.f;
#pragma unroll
    for (int i = 0; i < 8; i++) { int c = i * 32 + lane; v[i] = xr[c]; sum += v[i]; }
#pragma unroll
    for (int o = 16; o; o >>= 1) sum += __shfl_xor_sync(0xffffffffu, sum, o);
    float mean = sum * (1.f / 256.f);
    float s2 = 0.f;
#pragma unroll
    for (int i = 0; i < 8; i++) { float d = v[i] - mean; s2 += d * d; }
#pragma unroll
    for (int o = 16; o; o >>= 1) s2 += __shfl_xor_sync(0xffffffffu, s2, o);
    float rstd = rsqrtf(s2 * (1.f / 256.f) + 1e-5f);
    float* lr = lo + tok * 256;
#pragma unroll
    for (int i = 0; i < 8; i++) {
        int c = i * 32 + lane;
        float o = (v[i] - mean) * rstd * w[c] + bb[c];
        lr[c] = RND ? rnd_tf32(o) : o;
    }
}

// ---------------- pool + sine pos (rounded) ----------------
__global__ __launch_bounds__(256)
void pool_pos_k(const float* __restrict__ x, float* __restrict__ out)
{
    const int blk = blockIdx.x;
    const int b  = blk >> 8;
    const int ph = (blk >> 4) & 15;
    const int pw = blk & 15;
    const int c  = threadIdx.x;

    size_t base = ((size_t)(b * 128 + ph * 8) * 128 + pw * 8) * 256 + c;
    float s = 0.f;
#pragma unroll
    for (int i = 0; i < 8; i++)
#pragma unroll
        for (int j = 0; j < 8; j++)
            s += x[base + ((size_t)i * 128 + j) * 256];
    s *= (1.f / 64.f);

    float e; int cc;
    if (c < 128) { e = (float)(ph + 1); cc = c; }
    else         { e = (float)(pw + 1); cc = c - 128; }
    e = e / (16.f + 1e-5f) * 6.283185307179586f;
    float expo = (float)(cc & ~1) / 128.f;
    float tt = powf(10000.f, expo);
    float p = e / tt;
    float pe = (cc & 1) ? cosf(p) : sinf(p);
    out[(size_t)blk * 256 + c] = rnd_tf32(s + pe);
}

// ---------------- global attention ----------------
__global__ __launch_bounds__(256)
void glob_attn_k(const float* __restrict__ qkv, float* __restrict__ out)
{
    const int b = blockIdx.x >> 3;
    const int h = blockIdx.x & 7;
    __shared__ float ks[64][32], vs[64][32];

    const int t = threadIdx.x;
    float q[32];
    const float* qp = qkv + ((size_t)(b * 256 + t)) * 768 + h * 32;
#pragma unroll
    for (int d = 0; d < 32; d++) q[d] = qp[d] * SCALE_;

    float m = -1e30f, l = 0.f, acc[32];
#pragma unroll
    for (int d = 0; d < 32; d++) acc[d] = 0.f;

    for (int c0 = 0; c0 < 256; c0 += 64) {
        __syncthreads();
#pragma unroll
        for (int i = 0; i < 8; i++) {
            int e = i * 256 + t;
            int tk = e >> 5, d = e & 31;
            const float* p = qkv + ((size_t)(b * 256 + c0 + tk)) * 768 + h * 32 + d;
            ks[tk][d] = p[256];
            vs[tk][d] = p[512];
        }
        __syncthreads();
        for (int j = 0; j < 64; j++) {
            float sc = 0.f;
#pragma unroll
            for (int d = 0; d < 32; d++) sc = fmaf(q[d], ks[j][d], sc);
            float mn = fmaxf(m, sc);
            float corr = __expf(m - mn);
            float p = __expf(sc - mn);
            l = l * corr + p;
#pragma unroll
            for (int d = 0; d < 32; d++) acc[d] = acc[d] * corr + p * vs[j][d];
            m = mn;
        }
    }
    float inv = 1.f / l;
    float* op = out + ((size_t)(b * 256 + t)) * 256 + h * 32;
#pragma unroll
    for (int d = 0; d < 32; d++) op[d] = acc[d] * inv;
}

// ---------------- upsample + add + LN (ln rounded) ----------------
__global__ __launch_bounds__(256)
void up_add_ln_k(float* __restrict__ x, const float* __restrict__ g,
                 const float* __restrict__ w, const float* __restrict__ bb,
                 float* __restrict__ lo)
{
    const int warp = threadIdx.x >> 5, lane = threadIdx.x & 31;
    const size_t tok = (size_t)blockIdx.x * 8 + warp;
    const int b  = (int)(tok >> 14);
    const int y  = (int)((tok >> 7) & 127);
    const int xx = (int)(tok & 127);

    float sy = (float)y  * (15.f / 127.f);
    float sx = (float)xx * (15.f / 127.f);
    int y0 = (int)floorf(sy); if (y0 > 15) y0 = 15;
    int x0 = (int)floorf(sx); if (x0 > 15) x0 = 15;
    float ty = sy - (float)y0, tx = sx - (float)x0;
    int y1 = min(y0 + 1, 15), x1 = min(x0 + 1, 15);

    const float* g00 = g + ((size_t)((b * 16 + y0) * 16 + x0)) * 256;
    const float* g01 = g + ((size_t)((b * 16 + y0) * 16 + x1)) * 256;
    const float* g10 = g + ((size_t)((b * 16 + y1) * 16 + x0)) * 256;
    const float* g11 = g + ((size_t)((b * 16 + y1) * 16 + x1)) * 256;
    float w00 = (1.f - ty) * (1.f - tx), w01 = (1.f - ty) * tx;
    float w10 = ty * (1.f - tx),         w11 = ty * tx;

    float* xr = x + tok * 256;
    float v[8]; float sum = 0.f;
#pragma unroll
    for (int i = 0; i < 8; i++) {
        int c = i * 32 + lane;
        float up = g00[c] * w00 + g01[c] * w01 + g10[c] * w10 + g11[c] * w11;
        v[i] = xr[c] + up;
        sum += v[i];
    }
#pragma unroll
    for (int o = 16; o; o >>= 1) sum += __shfl_xor_sync(0xffffffffu, sum, o);
    float mean = sum * (1.f / 256.f);
    float s2 = 0.f;
#pragma unroll
    for (int i = 0; i < 8; i++) { float d = v[i] - mean; s2 += d * d; }
#pragma unroll
    for (int o = 16; o; o >>= 1) s2 += __shfl_xor_sync(0xffffffffu, s2, o);
    float rstd = rsqrtf(s2 * (1.f / 256.f) + 1e-5f);
    float* lr = lo + tok * 256;
#pragma unroll
    for (int i = 0; i < 8; i++) {
        int c = i * 32 + lane;
        xr[c] = v[i];
        lr[c] = rnd_tf32((v[i] - mean) * rstd * w[c] + bb[c]);
    }
}

// ---------------- launch ----------------
static float* symaddr(const void* sym)
{
    void* p = nullptr;
    cudaGetSymbolAddress(&p, sym);
    return (float*)p;
}
static void round_arr(const float* in, float* out, int n)
{
    int n4 = n / 4;
    round4_k<<<(n4 + 255) / 256, 256>>>((const float4*)in, (float4*)out, n4);
}

extern "C" void kernel_launch(void* const* d_in, const int* in_sizes, int n_in,
                              void* d_out, int out_size)
{
    const float* x          = (const float*)d_in[0];
    const float* rel_table  = (const float*)d_in[1];
    const float* qkv_w      = (const float*)d_in[2];
    const float* qkv_b      = (const float*)d_in[3];
    const float* qkv2_w     = (const float*)d_in[4];
    const float* qkv2_b     = (const float*)d_in[5];
    const float* proj_ln_w  = (const float*)d_in[6];
    const float* proj_ln_b  = (const float*)d_in[7];
    const float* proj_w     = (const float*)d_in[8];
    const float* proj_b     = (const float*)d_in[9];
    const float* proj2_ln_w = (const float*)d_in[10];
    const float* proj2_ln_b = (const float*)d_in[11];
    const float* proj2_w    = (const float*)d_in[12];
    const float* proj2_b    = (const float*)d_in[13];
    const float* norm1_w    = (const float*)d_in[14];
    const float* norm1_b    = (const float*)d_in[15];
    const float* norm2_w    = (const float*)d_in[16];
    const float* norm2_b    = (const float*)d_in[17];
    const float* fc1_w      = (const float*)d_in[18];
    const float* fc1_b      = (const float*)d_in[19];
    const float* fc2_w      = (const float*)d_in[20];
    const float* fc2_b      = (const float*)d_in[21];
    const int*   rel_idx    = (const int*)  d_in[22];

    float* qkv   = symaddr(g_qkv);
    float* attn  = symaddr(g_attn);
    float* xb    = symaddr(g_x);
    float* ln    = symaddr(g_ln);
    float* hbuf  = symaddr(g_h);
    float* pool  = symaddr(g_pool);
    float* qkvg  = symaddr(g_qkvg);
    float* attng = symaddr(g_attng);
    float* wr    = symaddr(g_wr);

    cudaFuncSetAttribute(mgemm_k<0>, cudaFuncAttributeMaxDynamicSharedMemorySize, MGEMM_SMEM);
    cudaFuncSetAttribute(mgemm_k<1>, cudaFuncAttributeMaxDynamicSharedMemorySize, MGEMM_SMEM);
    cudaFuncSetAttribute(mgemm_k<2>, cudaFuncAttributeMaxDynamicSharedMemorySize, MGEMM_SMEM);

    const int M = NTOK;

    // 0) pre-round weights + input x to tf32 (rna)
    round_arr(qkv_w,   wr + OFF_QKVW,  768 * 256);
    round_arr(proj_w,  wr + OFF_PROJW, 256 * 256);
    round_arr(proj2_w, wr + OFF_PROJ2W,256 * 256);
    round_arr(fc1_w,   wr + OFF_FC1W,  1024 * 256);
    round_arr(fc2_w,   wr + OFF_FC2W,  256 * 1024);
    round_arr(qkv2_w,  wr + OFF_QKV2W, 768 * 256);
    round_arr(x, attn, M * 256);

    // 1) window-branch QKV (grid: n fastest)
    mgemm_k<0><<<dim3(6, M/128), 256, MGEMM_SMEM>>>(attn, wr + OFF_QKVW, qkv_b, nullptr, qkv, M, 768, 256);
    // 2) window attention
    win_attn_k<<<dim3(2048, 8), 256>>>(qkv, rel_table, rel_idx, attn);
    // 3) x = x + attn ; ln = LN(x)
    add_ln_k<<<M/8, 256>>>(x, attn, proj_ln_w, proj_ln_b, xb, ln);
    // 4) x += ln @ proj_w^T + proj_b
    mgemm_k<1><<<dim3(2, M/128), 256, MGEMM_SMEM>>>(ln, wr + OFF_PROJW, proj_b, xb, xb, M, 256, 256);
    // 5) pool + sine pos
    pool_pos_k<<<2048, 256>>>(xb, pool);
    // 6) global QKV
    mgemm_k<0><<<dim3(6, 16), 256, MGEMM_SMEM>>>(pool, wr + OFF_QKV2W, qkv2_b, nullptr, qkvg, 2048, 768, 256);
    // 7) global attention
    glob_attn_k<<<64, 256>>>(qkvg, attng);
    // 8) x += upsample(attng) ; ln = LN(x)
    up_add_ln_k<<<M/8, 256>>>(xb, attng, proj2_ln_w, proj2_ln_b, ln);
    // 9) x += ln @ proj2_w^T + proj2_b
    mgemm_k<1><<<dim3(2, M/128), 256, MGEMM_SMEM>>>(ln, wr + OFF_PROJ2W, proj2_b, xb, xb, M, 256, 256);
    // 10) ln = LN(x, norm1)
    ln_k<1><<<M/8, 256>>>(xb, norm1_w, norm1_b, ln);
    // 11) h = gelu(ln @ fc1^T)
    mgemm_k<2><<<dim3(8, M/128), 256, MGEMM_SMEM>>>(ln, wr + OFF_FC1W, fc1_b, nullptr, hbuf, M, 1024, 256);
    // 12) x += h @ fc2^T
    mgemm_k<1><<<dim3(2, M/128), 256, MGEMM_SMEM>>>(hbuf, wr + OFF_FC2W, fc2_b, xb, xb, M, 256, 1024);
    // 13) out = LN(x, norm2)
    ln_k<0><<<M/8, 256>>>(xb, norm2_w, norm2_b, (float*)d_out);
}

// round 11
// speedup vs baseline: 1.1049x; 1.1049x over previous
#include <cuda_runtime.h>
#include <cuda_bf16.h>
#include <math.h>
#include <stdint.h>

#define DIM 256
#define HEADS 8
#define WS 8
#define B_ 8
#define NTOK (B_*128*128)          // 131072
#define MLP_HIDDEN 1024
#define SCALE_ 0.17677669529663687f

// ---------------- scratch ----------------
__device__ float g_qkv [NTOK * 768];
__device__ float g_attn[NTOK * DIM];          // rounded-x for qkv GEMM input
__device__ float g_x   [NTOK * DIM];
__device__ float g_ln  [NTOK * DIM];
__device__ float g_h   [NTOK * MLP_HIDDEN];
__device__ float g_pool [B_ * 256 * DIM];
__device__ float g_qkvg [B_ * 256 * 768];
__device__ float g_attng[B_ * 256 * DIM];
__device__ float g_wr  [1048576];             // rounded weights

#define OFF_QKVW  0
#define OFF_PROJW 196608
#define OFF_PROJ2W 262144
#define OFF_FC1W  327680
#define OFF_FC2W  589824
#define OFF_QKV2W 851968

// ---------------- helpers ----------------
__device__ __forceinline__ uint32_t smem_u32(const void* p) {
    uint32_t a;
    asm("{ .reg .u64 t; cvta.to.shared.u64 t, %1; cvt.u32.u64 %0, t; }" : "=r"(a) : "l"(p));
    return a;
}
#define CP16(dst, src) \
    asm volatile("cp.async.cg.shared.global [%0], [%1], 16;" :: "r"(dst), "l"(src))
#define CP_COMMIT() asm volatile("cp.async.commit_group;" ::: "memory")
#define CP_WAIT1()  asm volatile("cp.async.wait_group 1;" ::: "memory")

__device__ __forceinline__ uint32_t f2tf32(float f) {
    uint32_t u;
    asm("cvt.rna.tf32.f32 %0, %1;" : "=r"(u) : "f"(f));
    return u;
}
__device__ __forceinline__ float rnd_tf32(float f) {
    return __uint_as_float(f2tf32(f));
}
__device__ __forceinline__ void mma_tf32(float* d, float a0, float a1, float a2, float a3,
                                         float b0, float b1) {
    asm volatile(
        "mma.sync.aligned.m16n8k8.row.col.f32.tf32.tf32.f32 "
        "{%0,%1,%2,%3}, {%4,%5,%6,%7}, {%8,%9}, {%0,%1,%2,%3};"
        : "+f"(d[0]), "+f"(d[1]), "+f"(d[2]), "+f"(d[3])
        : "r"(__float_as_uint(a0)), "r"(__float_as_uint(a1)),
          "r"(__float_as_uint(a2)), "r"(__float_as_uint(a3)),
          "r"(__float_as_uint(b0)), "r"(__float_as_uint(b1)));
}

// ---------------- tf32 round kernel ----------------
__global__ __launch_bounds__(256)
void round4_k(const float4* __restrict__ in, float4* __restrict__ out, int n4)
{
    int i = blockIdx.x * 256 + threadIdx.x;
    if (i < n4) {
        float4 v = in[i];
        v.x = rnd_tf32(v.x); v.y = rnd_tf32(v.y);
        v.z = rnd_tf32(v.z); v.w = rnd_tf32(v.w);
        out[i] = v;
    }
}

// ---------------- tf32 mma.sync GEMM (R5 tile/pipeline; n-fastest grid) ---------
// C[M,N] = A[M,K] @ B[N,K]^T + bias (+epi); A,B pre-rounded to tf32
// grid: x = n-block (fastest => A m-tile L2 reuse), y = m-block
// EPI: 0 none, 1 +res, 2 gelu(exact, rounded output)
#define BM 128
#define BN 128
#define BK 32
#define STG 3
#define APAD 36
#define ASZ (BM*APAD)
#define BSZ (BN*APAD)
#define STAGE_F (ASZ + BSZ)
#define MGEMM_SMEM (STG * STAGE_F * 4)   // 110592 B

__device__ __forceinline__ void load_tile(const float* __restrict__ Ag,
                                          const float* __restrict__ Bg,
                                          int K, uint32_t sA, uint32_t sB, int t)
{
#pragma unroll
    for (int i = 0; i < 4; i++) {
        int idx = i * 256 + t;
        int row = idx >> 3, ch = idx & 7;
        CP16(sA + row * (APAD * 4) + ch * 16, Ag + (size_t)row * K + ch * 4);
    }
#pragma unroll
    for (int i = 0; i < 4; i++) {
        int idx = i * 256 + t;
        int row = idx >> 3, ch = idx & 7;
        CP16(sB + row * (APAD * 4) + ch * 16, Bg + (size_t)row * K + ch * 4);
    }
}

template<int EPI>
__global__ __launch_bounds__(256)
void mgemm_k(const float* __restrict__ A, const float* __restrict__ Bw,
             const float* __restrict__ bias, const float* __restrict__ res,
             float* __restrict__ C, int M, int N, int K)
{
    extern __shared__ float sm[];
    const uint32_t smb = smem_u32(sm);

    const int t = threadIdx.x, lane = t & 31, warp = t >> 5;
    const int wm = warp >> 1, wn = warp & 1;
    const int bm = blockIdx.y * BM, bn = blockIdx.x * BN;   // n fastest
    const int nk = K / BK;
    const int r = lane >> 2, cq = lane & 3;

    float acc[2][8][4];
#pragma unroll
    for (int i = 0; i < 2; i++)
#pragma unroll
        for (int j = 0; j < 8; j++)
#pragma unroll
            for (int q = 0; q < 4; q++) acc[i][j][q] = 0.f;

    const float* Abase = A + (size_t)bm * K;
    const float* Bbase = Bw + (size_t)bn * K;

#pragma unroll
    for (int s = 0; s < STG - 1; s++) {
        load_tile(Abase + s * BK, Bbase + s * BK, K,
                  smb + s * STAGE_F * 4, smb + (s * STAGE_F + ASZ) * 4, t);
        CP_COMMIT();
    }

    for (int kt = 0; kt < nk; kt++) {
        CP_WAIT1();
        __syncthreads();
        const int pf = kt + STG - 1;
        if (pf < nk) {
            const int st = pf % STG;
            load_tile(Abase + pf * BK, Bbase + pf * BK, K,
                      smb + st * STAGE_F * 4, smb + (st * STAGE_F + ASZ) * 4, t);
        }
        CP_COMMIT();

        const float* sA = sm + (kt % STG) * STAGE_F;
        const float* sB = sA + ASZ;
#pragma unroll
        for (int ks = 0; ks < 4; ks++) {
            const int k0 = ks * 8;
            float a[2][4];
#pragma unroll
            for (int mi = 0; mi < 2; mi++) {
                const int row = wm * 32 + mi * 16;
                a[mi][0] = sA[(row + r)     * APAD + k0 + cq];
                a[mi][1] = sA[(row + r + 8) * APAD + k0 + cq];
                a[mi][2] = sA[(row + r)     * APAD + k0 + cq + 4];
                a[mi][3] = sA[(row + r + 8) * APAD + k0 + cq + 4];
            }
            float b[8][2];
#pragma unroll
            for (int ni = 0; ni < 8; ni++) {
                const int col = wn * 64 + ni * 8;
                b[ni][0] = sB[(col + r) * APAD + k0 + cq];
                b[ni][1] = sB[(col + r) * APAD + k0 + cq + 4];
            }
#pragma unroll
            for (int mi = 0; mi < 2; mi++)
#pragma unroll
                for (int ni = 0; ni < 8; ni++)
                    mma_tf32(acc[mi][ni], a[mi][0], a[mi][1], a[mi][2], a[mi][3],
                             b[ni][0], b[ni][1]);
        }
    }

    // epilogue
#pragma unroll
    for (int ni = 0; ni < 8; ni++) {
        const int col = bn + wn * 64 + ni * 8 + cq * 2;
        const float b0 = bias[col], b1 = bias[col + 1];
#pragma unroll
        for (int mi = 0; mi < 2; mi++) {
            const int row0 = bm + wm * 32 + mi * 16 + r;
#pragma unroll
            for (int h = 0; h < 2; h++) {
                const int row = row0 + h * 8;
                float2 o;
                o.x = acc[mi][ni][h * 2 + 0] + b0;
                o.y = acc[mi][ni][h * 2 + 1] + b1;
                const size_t off = (size_t)row * N + col;
                if (EPI == 1) {
                    const float2 rr = *(const float2*)(res + off);
                    o.x += rr.x; o.y += rr.y;
                }
                if (EPI == 2) {
                    o.x = rnd_tf32(0.5f * o.x * (1.f + erff(o.x * 0.70710678118654752f)));
                    o.y = rnd_tf32(0.5f * o.y * (1.f + erff(o.y * 0.70710678118654752f)));
                }
                *(float2*)(C + off) = o;
            }
        }
    }
}

// ---------------- window attention (+ fused residual add of original x) --------
__global__ __launch_bounds__(256)
void win_attn_k(const float* __restrict__ qkv, const float* __restrict__ rel_table,
                const int* __restrict__ rel_idx, const float* __restrict__ xin,
                float* __restrict__ out)
{
    const int win = blockIdx.x;
    const int h   = blockIdx.y;
    const int b   = win >> 8;
    const int wr  = (win >> 4) & 15;
    const int wc  = win & 15;

    __shared__ float q[64][33], k[64][33], v[64][33];
    __shared__ float s[64][65];

    const int t = threadIdx.x;
#pragma unroll
    for (int i = 0; i < 8; i++) {
        int e = i * 256 + t;
        int tok = e >> 5, d = e & 31;
        int ti = tok >> 3, tj = tok & 7;
        size_t row = ((size_t)(b * 128 + wr * 8 + ti) * 128 + (wc * 8 + tj));
        const float* base = qkv + row * 768 + h * 32 + d;
        q[tok][d] = base[0];
        k[tok][d] = base[256];
        v[tok][d] = base[512];
    }
    __syncthreads();

    const int qi = t >> 2;
    const int j0 = (t & 3) * 16;
#pragma unroll
    for (int j = j0; j < j0 + 16; j++) {
        float a = 0.f;
#pragma unroll
        for (int d = 0; d < 32; d++) a = fmaf(q[qi][d], k[j][d], a);
        s[qi][j] = a * SCALE_ + rel_table[rel_idx[qi * 64 + j] * HEADS + h];
    }
    __syncthreads();

    const int warp = t >> 5, lane = t & 31;
    for (int r = warp * 8; r < warp * 8 + 8; r++) {
        float a = s[r][lane], bvv = s[r][lane + 32];
        float mx = fmaxf(a, bvv);
#pragma unroll
        for (int o = 16; o; o >>= 1) mx = fmaxf(mx, __shfl_xor_sync(0xffffffffu, mx, o));
        a = __expf(a - mx); bvv = __expf(bvv - mx);
        float sum = a + bvv;
#pragma unroll
        for (int o = 16; o; o >>= 1) sum += __shfl_xor_sync(0xffffffffu, sum, o);
        float inv = 1.f / sum;
        s[r][lane] = a * inv; s[r][lane + 32] = bvv * inv;
    }
    __syncthreads();

    const int d0 = (t & 3) * 8;
    float acc[8];
#pragma unroll
    for (int dd = 0; dd < 8; dd++) acc[dd] = 0.f;
    for (int j = 0; j < 64; j++) {
        float p = s[qi][j];
#pragma unroll
        for (int dd = 0; dd < 8; dd++) acc[dd] = fmaf(p, v[j][d0 + dd], acc[dd]);
    }
    int ti = qi >> 3, tj = qi & 7;
    size_t row = ((size_t)(b * 128 + wr * 8 + ti) * 128 + (wc * 8 + tj));
    const float* xr = xin + row * 256 + h * 32 + d0;
    float* ob = out + row * 256 + h * 32 + d0;
#pragma unroll
    for (int dd = 0; dd < 8; dd++) ob[dd] = acc[dd] + xr[dd];
}

// ---------------- LN only; RND=1 rounds output (GEMM input) --------------------
template<int RND>
__global__ __launch_bounds__(256)
void ln_k(const float* __restrict__ x, const float* __restrict__ w,
          const float* __restrict__ bb, float* __restrict__ lo)
{
    const int warp = threadIdx.x >> 5, lane = threadIdx.x & 31;
    const size_t tok = (size_t)blockIdx.x * 8 + warp;
    const float* xr = x + tok * 256;
    float v[8]; float sum = 0.f;
#pragma unroll
    for (int i = 0; i < 8; i++) { int c = i * 32 + lane; v[i] = xr[c]; sum += v[i]; }
#pragma unroll
    for (int o = 16; o; o >>= 1) sum += __shfl_xor_sync(0xffffffffu, sum, o);
    float mean = sum * (1.f / 256.f);
    float s2 = 0.f;
#pragma unroll
    for (int i = 0; i < 8; i++) { float d = v[i] - mean; s2 += d * d; }
#pragma unroll
    for (int o = 16; o; o >>= 1) s2 += __shfl_xor_sync(0xffffffffu, s2, o);
    float rstd = rsqrtf(s2 * (1.f / 256.f) + 1e-5f);
    float* lr = lo + tok * 256;
#pragma unroll
    for (int i = 0; i < 8; i++) {
        int c = i * 32 + lane;
        float o = (v[i] - mean) * rstd * w[c] + bb[c];
        lr[c] = RND ? rnd_tf32(o) : o;
    }
}

// ---------------- pool + sine pos (rounded) ----------------
__global__ __launch_bounds__(256)
void pool_pos_k(const float* __restrict__ x, float* __restrict__ out)
{
    const int blk = blockIdx.x;
    const int b  = blk >> 8;
    const int ph = (blk >> 4) & 15;
    const int pw = blk & 15;
    const int c  = threadIdx.x;

    size_t base = ((size_t)(b * 128 + ph * 8) * 128 + pw * 8) * 256 + c;
    float s = 0.f;
#pragma unroll
    for (int i = 0; i < 8; i++)
#pragma unroll
        for (int j = 0; j < 8; j++)
            s += x[base + ((size_t)i * 128 + j) * 256];
    s *= (1.f / 64.f);

    float e; int cc;
    if (c < 128) { e = (float)(ph + 1); cc = c; }
    else         { e = (float)(pw + 1); cc = c - 128; }
    e = e / (16.f + 1e-5f) * 6.283185307179586f;
    float expo = (float)(cc & ~1) / 128.f;
    float tt = powf(10000.f, expo);
    float p = e / tt;
    float pe = (cc & 1) ? cosf(p) : sinf(p);
    out[(size_t)blk * 256 + c] = rnd_tf32(s + pe);
}

// ---------------- global attention ----------------
__global__ __launch_bounds__(256)
void glob_attn_k(const float* __restrict__ qkv, float* __restrict__ out)
{
    const int b = blockIdx.x >> 3;
    const int h = blockIdx.x & 7;
    __shared__ float ks[64][32], vs[64][32];

    const int t = threadIdx.x;
    float q[32];
    const float* qp = qkv + ((size_t)(b * 256 + t)) * 768 + h * 32;
#pragma unroll
    for (int d = 0; d < 32; d++) q[d] = qp[d] * SCALE_;

    float m = -1e30f, l = 0.f, acc[32];
#pragma unroll
    for (int d = 0; d < 32; d++) acc[d] = 0.f;

    for (int c0 = 0; c0 < 256; c0 += 64) {
        __syncthreads();
#pragma unroll
        for (int i = 0; i < 8; i++) {
            int e = i * 256 + t;
            int tk = e >> 5, d = e & 31;
            const float* p = qkv + ((size_t)(b * 256 + c0 + tk)) * 768 + h * 32 + d;
            ks[tk][d] = p[256];
            vs[tk][d] = p[512];
        }
        __syncthreads();
        for (int j = 0; j < 64; j++) {
            float sc = 0.f;
#pragma unroll
            for (int d = 0; d < 32; d++) sc = fmaf(q[d], ks[j][d], sc);
            float mn = fmaxf(m, sc);
            float corr = __expf(m - mn);
            float p = __expf(sc - mn);
            l = l * corr + p;
#pragma unroll
            for (int d = 0; d < 32; d++) acc[d] = acc[d] * corr + p * vs[j][d];
            m = mn;
        }
    }
    float inv = 1.f / l;
    float* op = out + ((size_t)(b * 256 + t)) * 256 + h * 32;
#pragma unroll
    for (int d = 0; d < 32; d++) op[d] = acc[d] * inv;
}

// ---------------- upsample + add + LN (ln rounded) ----------------
__global__ __launch_bounds__(256)
void up_add_ln_k(float* __restrict__ x, const float* __restrict__ g,
                 const float* __restrict__ w, const float* __restrict__ bb,
                 float* __restrict__ lo)
{
    const int warp = threadIdx.x >> 5, lane = threadIdx.x & 31;
    const size_t tok = (size_t)blockIdx.x * 8 + warp;
    const int b  = (int)(tok >> 14);
    const int y  = (int)((tok >> 7) & 127);
    const int xx = (int)(tok & 127);

    float sy = (float)y  * (15.f / 127.f);
    float sx = (float)xx * (15.f / 127.f);
    int y0 = (int)floorf(sy); if (y0 > 15) y0 = 15;
    int x0 = (int)floorf(sx); if (x0 > 15) x0 = 15;
    float ty = sy - (float)y0, tx = sx - (float)x0;
    int y1 = min(y0 + 1, 15), x1 = min(x0 + 1, 15);

    const float* g00 = g + ((size_t)((b * 16 + y0) * 16 + x0)) * 256;
    const float* g01 = g + ((size_t)((b * 16 + y0) * 16 + x1)) * 256;
    const float* g10 = g + ((size_t)((b * 16 + y1) * 16 + x0)) * 256;
    const float* g11 = g + ((size_t)((b * 16 + y1) * 16 + x1)) * 256;
    float w00 = (1.f - ty) * (1.f - tx), w01 = (1.f - ty) * tx;
    float w10 = ty * (1.f - tx),         w11 = ty * tx;

    float* xr = x + tok * 256;
    float v[8]; float sum = 0.f;
#pragma unroll
    for (int i = 0; i < 8; i++) {
        int c = i * 32 + lane;
        float up = g00[c] * w00 + g01[c] * w01 + g10[c] * w10 + g11[c] * w11;
        v[i] = xr[c] + up;
        sum += v[i];
    }
#pragma unroll
    for (int o = 16; o; o >>= 1) sum += __shfl_xor_sync(0xffffffffu, sum, o);
    float mean = sum * (1.f / 256.f);
    float s2 = 0.f;
#pragma unroll
    for (int i = 0; i < 8; i++) { float d = v[i] - mean; s2 += d * d; }
#pragma unroll
    for (int o = 16; o; o >>= 1) s2 += __shfl_xor_sync(0xffffffffu, s2, o);
    float rstd = rsqrtf(s2 * (1.f / 256.f) + 1e-5f);
    float* lr = lo + tok * 256;
#pragma unroll
    for (int i = 0; i < 8; i++) {
        int c = i * 32 + lane;
        xr[c] = v[i];
        lr[c] = rnd_tf32((v[i] - mean) * rstd * w[c] + bb[c]);
    }
}

// ---------------- launch ----------------
static float* symaddr(const void* sym)
{
    void* p = nullptr;
    cudaGetSymbolAddress(&p, sym);
    return (float*)p;
}
static void round_arr(const float* in, float* out, int n)
{
    int n4 = n / 4;
    round4_k<<<(n4 + 255) / 256, 256>>>((const float4*)in, (float4*)out, n4);
}

extern "C" void kernel_launch(void* const* d_in, const int* in_sizes, int n_in,
                              void* d_out, int out_size)
{
    const float* x          = (const float*)d_in[0];
    const float* rel_table  = (const float*)d_in[1];
    const float* qkv_w      = (const float*)d_in[2];
    const float* qkv_b      = (const float*)d_in[3];
    const float* qkv2_w     = (const float*)d_in[4];
    const float* qkv2_b     = (const float*)d_in[5];
    const float* proj_ln_w  = (const float*)d_in[6];
    const float* proj_ln_b  = (const float*)d_in[7];
    const float* proj_w     = (const float*)d_in[8];
    const float* proj_b     = (const float*)d_in[9];
    const float* proj2_ln_w = (const float*)d_in[10];
    const float* proj2_ln_b = (const float*)d_in[11];
    const float* proj2_w    = (const float*)d_in[12];
    const float* proj2_b    = (const float*)d_in[13];
    const float* norm1_w    = (const float*)d_in[14];
    const float* norm1_b    = (const float*)d_in[15];
    const float* norm2_w    = (const float*)d_in[16];
    const float* norm2_b    = (const float*)d_in[17];
    const float* fc1_w      = (const float*)d_in[18];
    const float* fc1_b      = (const float*)d_in[19];
    const float* fc2_w      = (const float*)d_in[20];
    const float* fc2_b      = (const float*)d_in[21];
    const int*   rel_idx    = (const int*)  d_in[22];

    float* qkv   = symaddr(g_qkv);
    float* attn  = symaddr(g_attn);
    float* xb    = symaddr(g_x);
    float* ln    = symaddr(g_ln);
    float* hbuf  = symaddr(g_h);
    float* pool  = symaddr(g_pool);
    float* qkvg  = symaddr(g_qkvg);
    float* attng = symaddr(g_attng);
    float* wr    = symaddr(g_wr);

    cudaFuncSetAttribute(mgemm_k<0>, cudaFuncAttributeMaxDynamicSharedMemorySize, MGEMM_SMEM);
    cudaFuncSetAttribute(mgemm_k<1>, cudaFuncAttributeMaxDynamicSharedMemorySize, MGEMM_SMEM);
    cudaFuncSetAttribute(mgemm_k<2>, cudaFuncAttributeMaxDynamicSharedMemorySize, MGEMM_SMEM);

    const int M = NTOK;

    // 0) pre-round weights + input x to tf32 (rna)
    round_arr(qkv_w,   wr + OFF_QKVW,  768 * 256);
    round_arr(proj_w,  wr + OFF_PROJW, 256 * 256);
    round_arr(proj2_w, wr + OFF_PROJ2W,256 * 256);
    round_arr(fc1_w,   wr + OFF_FC1W,  1024 * 256);
    round_arr(fc2_w,   wr + OFF_FC2W,  256 * 1024);
    round_arr(qkv2_w,  wr + OFF_QKV2W, 768 * 256);
    round_arr(x, attn, M * 256);

    // 1) window-branch QKV (grid: n fastest for A reuse)
    mgemm_k<0><<<dim3(6, M/128), 256, MGEMM_SMEM>>>(attn, wr + OFF_QKVW, qkv_b, nullptr, qkv, M, 768, 256);
    // 2) window attention + fused residual (writes xb = x + attn)
    win_attn_k<<<dim3(2048, 8), 256>>>(qkv, rel_table, rel_idx, x, xb);
    // 3) ln = LN(xb) (rounded)
    ln_k<1><<<M/8, 256>>>(xb, proj_ln_w, proj_ln_b, ln);
    // 4) x += ln @ proj_w^T + proj_b
    mgemm_k<1><<<dim3(2, M/128), 256, MGEMM_SMEM>>>(ln, wr + OFF_PROJW, proj_b, xb, xb, M, 256, 256);
    // 5) pool + sine pos
    pool_pos_k<<<2048, 256>>>(xb, pool);
    // 6) global QKV
    mgemm_k<0><<<dim3(6, 16), 256, MGEMM_SMEM>>>(pool, wr + OFF_QKV2W, qkv2_b, nullptr, qkvg, 2048, 768, 256);
    // 7) global attention
    glob_attn_k<<<64, 256>>>(qkvg, attng);
    // 8) x += upsample(attng) ; ln = LN(x)
    up_add_ln_k<<<M/8, 256>>>(xb, attng, proj2_ln_w, proj2_ln_b, ln);
    // 9) x += ln @ proj2_w^T + proj2_b
    mgemm_k<1><<<dim3(2, M/128), 256, MGEMM_SMEM>>>(ln, wr + OFF_PROJ2W, proj2_b, xb, xb, M, 256, 256);
    // 10) ln = LN(x, norm1)
    ln_k<1><<<M/8, 256>>>(xb, norm1_w, norm1_b, ln);
    // 11) h = gelu(ln @ fc1^T)
    mgemm_k<2><<<dim3(8, M/128), 256, MGEMM_SMEM>>>(ln, wr + OFF_FC1W, fc1_b, nullptr, hbuf, M, 1024, 256);
    // 12) x += h @ fc2^T
    mgemm_k<1><<<dim3(2, M/128), 256, MGEMM_SMEM>>>(hbuf, wr + OFF_FC2W, fc2_b, xb, xb, M, 256, 1024);
    // 13) out = LN(x, norm2)
    ln_k<0><<<M/8, 256>>>(xb, norm2_w, norm2_b, (float*)d_out);
}

// round 13
// speedup vs baseline: 1.1362x; 1.0283x over previous
#include <cuda_runtime.h>
#include <cuda_bf16.h>
#include <math.h>
#include <stdint.h>

#define DIM 256
#define HEADS 8
#define WS 8
#define B_ 8
#define NTOK (B_*128*128)          // 131072
#define MLP_HIDDEN 1024
#define SCALE_ 0.17677669529663687f

// ---------------- scratch ----------------
__device__ float g_qkv [NTOK * 768];
__device__ float g_attn[NTOK * DIM];          // rounded-x for qkv GEMM input
__device__ float g_x   [NTOK * DIM];
__device__ float g_ln  [NTOK * DIM];
__device__ __nv_bfloat16 g_h16 [NTOK * MLP_HIDDEN];
__device__ float g_pool [B_ * 256 * DIM];
__device__ float g_qkvg [B_ * 256 * 768];
__device__ float g_attng[B_ * 256 * DIM];
__device__ float g_wr  [786432];              // tf32-rounded weights
__device__ __nv_bfloat16 g_wr16[262144];      // bf16 fc2 weights

#define OFF_QKVW  0
#define OFF_PROJW 196608
#define OFF_PROJ2W 262144
#define OFF_FC1W  327680
#define OFF_QKV2W 589824

// ---------------- helpers ----------------
__device__ __forceinline__ uint32_t smem_u32(const void* p) {
    uint32_t a;
    asm("{ .reg .u64 t; cvta.to.shared.u64 t, %1; cvt.u32.u64 %0, t; }" : "=r"(a) : "l"(p));
    return a;
}
#define CP16(dst, src) \
    asm volatile("cp.async.cg.shared.global [%0], [%1], 16;" :: "r"(dst), "l"(src))
#define CP_COMMIT() asm volatile("cp.async.commit_group;" ::: "memory")
#define CP_WAIT1()  asm volatile("cp.async.wait_group 1;" ::: "memory")

__device__ __forceinline__ uint32_t f2tf32(float f) {
    uint32_t u;
    asm("cvt.rna.tf32.f32 %0, %1;" : "=r"(u) : "f"(f));
    return u;
}
__device__ __forceinline__ float rnd_tf32(float f) {
    return __uint_as_float(f2tf32(f));
}
__device__ __forceinline__ void mma_tf32(float* d, float a0, float a1, float a2, float a3,
                                         float b0, float b1) {
    asm volatile(
        "mma.sync.aligned.m16n8k8.row.col.f32.tf32.tf32.f32 "
        "{%0,%1,%2,%3}, {%4,%5,%6,%7}, {%8,%9}, {%0,%1,%2,%3};"
        : "+f"(d[0]), "+f"(d[1]), "+f"(d[2]), "+f"(d[3])
        : "r"(__float_as_uint(a0)), "r"(__float_as_uint(a1)),
          "r"(__float_as_uint(a2)), "r"(__float_as_uint(a3)),
          "r"(__float_as_uint(b0)), "r"(__float_as_uint(b1)));
}
__device__ __forceinline__ void mma_bf16(float* d, uint32_t a0, uint32_t a1, uint32_t a2,
                                         uint32_t a3, uint32_t b0, uint32_t b1) {
    asm volatile(
        "mma.sync.aligned.m16n8k16.row.col.f32.bf16.bf16.f32 "
        "{%0,%1,%2,%3}, {%4,%5,%6,%7}, {%8,%9}, {%0,%1,%2,%3};"
        : "+f"(d[0]), "+f"(d[1]), "+f"(d[2]), "+f"(d[3])
        : "r"(a0), "r"(a1), "r"(a2), "r"(a3), "r"(b0), "r"(b1));
}

// ---------------- rounding kernels ----------------
__global__ __launch_bounds__(256)
void round4_k(const float4* __restrict__ in, float4* __restrict__ out, int n4)
{
    int i = blockIdx.x * 256 + threadIdx.x;
    if (i < n4) {
        float4 v = in[i];
        v.x = rnd_tf32(v.x); v.y = rnd_tf32(v.y);
        v.z = rnd_tf32(v.z); v.w = rnd_tf32(v.w);
        out[i] = v;
    }
}
__global__ __launch_bounds__(256)
void round16_k(const float4* __restrict__ in, uint2* __restrict__ out, int n4)
{
    int i = blockIdx.x * 256 + threadIdx.x;
    if (i < n4) {
        float4 v = in[i];
        __nv_bfloat162 p0 = __floats2bfloat162_rn(v.x, v.y);
        __nv_bfloat162 p1 = __floats2bfloat162_rn(v.z, v.w);
        uint2 o;
        o.x = *(uint32_t*)&p0;
        o.y = *(uint32_t*)&p1;
        out[i] = o;
    }
}

// ---------------- tf32 mma.sync GEMM (R11 proven config) ------------------------
// EPI: 0 none (fp32 C), 1 +res (fp32 C), 2 gelu -> bf16 C
#define BM 128
#define BN 128
#define BK 32
#define STG 3
#define APAD 36
#define ASZ (BM*APAD)
#define BSZ (BN*APAD)
#define STAGE_F (ASZ + BSZ)
#define MGEMM_SMEM (STG * STAGE_F * 4)   // 110592 B

__device__ __forceinline__ void load_tile(const float* __restrict__ Ag,
                                          const float* __restrict__ Bg,
                                          int K, uint32_t sA, uint32_t sB, int t)
{
#pragma unroll
    for (int i = 0; i < 4; i++) {
        int idx = i * 256 + t;
        int row = idx >> 3, ch = idx & 7;
        CP16(sA + row * (APAD * 4) + ch * 16, Ag + (size_t)row * K + ch * 4);
    }
#pragma unroll
    for (int i = 0; i < 4; i++) {
        int idx = i * 256 + t;
        int row = idx >> 3, ch = idx & 7;
        CP16(sB + row * (APAD * 4) + ch * 16, Bg + (size_t)row * K + ch * 4);
    }
}

template<int EPI>
__global__ __launch_bounds__(256)
void mgemm_k(const float* __restrict__ A, const float* __restrict__ Bw,
             const float* __restrict__ bias, const float* __restrict__ res,
             void* __restrict__ Cv, int M, int N, int K)
{
    extern __shared__ float sm[];
    const uint32_t smb = smem_u32(sm);

    const int t = threadIdx.x, lane = t & 31, warp = t >> 5;
    const int wm = warp >> 1, wn = warp & 1;
    const int bm = blockIdx.y * BM, bn = blockIdx.x * BN;   // n fastest
    const int nk = K / BK;
    const int r = lane >> 2, cq = lane & 3;

    float acc[2][8][4];
#pragma unroll
    for (int i = 0; i < 2; i++)
#pragma unroll
        for (int j = 0; j < 8; j++)
#pragma unroll
            for (int q = 0; q < 4; q++) acc[i][j][q] = 0.f;

    const float* Abase = A + (size_t)bm * K;
    const float* Bbase = Bw + (size_t)bn * K;

#pragma unroll
    for (int s = 0; s < STG - 1; s++) {
        load_tile(Abase + s * BK, Bbase + s * BK, K,
                  smb + s * STAGE_F * 4, smb + (s * STAGE_F + ASZ) * 4, t);
        CP_COMMIT();
    }

    for (int kt = 0; kt < nk; kt++) {
        CP_WAIT1();
        __syncthreads();
        const int pf = kt + STG - 1;
        if (pf < nk) {
            const int st = pf % STG;
            load_tile(Abase + pf * BK, Bbase + pf * BK, K,
                      smb + st * STAGE_F * 4, smb + (st * STAGE_F + ASZ) * 4, t);
        }
        CP_COMMIT();

        const float* sA = sm + (kt % STG) * STAGE_F;
        const float* sB = sA + ASZ;
#pragma unroll
        for (int ks = 0; ks < 4; ks++) {
            const int k0 = ks * 8;
            float a[2][4];
#pragma unroll
            for (int mi = 0; mi < 2; mi++) {
                const int row = wm * 32 + mi * 16;
                a[mi][0] = sA[(row + r)     * APAD + k0 + cq];
                a[mi][1] = sA[(row + r + 8) * APAD + k0 + cq];
                a[mi][2] = sA[(row + r)     * APAD + k0 + cq + 4];
                a[mi][3] = sA[(row + r + 8) * APAD + k0 + cq + 4];
            }
            float b[8][2];
#pragma unroll
            for (int ni = 0; ni < 8; ni++) {
                const int col = wn * 64 + ni * 8;
                b[ni][0] = sB[(col + r) * APAD + k0 + cq];
                b[ni][1] = sB[(col + r) * APAD + k0 + cq + 4];
            }
#pragma unroll
            for (int mi = 0; mi < 2; mi++)
#pragma unroll
                for (int ni = 0; ni < 8; ni++)
                    mma_tf32(acc[mi][ni], a[mi][0], a[mi][1], a[mi][2], a[mi][3],
                             b[ni][0], b[ni][1]);
        }
    }

    // epilogue
    float* Cf = (float*)Cv;
    __nv_bfloat16* Ch = (__nv_bfloat16*)Cv;
#pragma unroll
    for (int ni = 0; ni < 8; ni++) {
        const int col = bn + wn * 64 + ni * 8 + cq * 2;
        const float b0 = bias[col], b1 = bias[col + 1];
#pragma unroll
        for (int mi = 0; mi < 2; mi++) {
            const int row0 = bm + wm * 32 + mi * 16 + r;
#pragma unroll
            for (int h = 0; h < 2; h++) {
                const int row = row0 + h * 8;
                float ox = acc[mi][ni][h * 2 + 0] + b0;
                float oy = acc[mi][ni][h * 2 + 1] + b1;
                const size_t off = (size_t)row * N + col;
                if (EPI == 1) {
                    const float2 rr = *(const float2*)(res + off);
                    ox += rr.x; oy += rr.y;
                }
                if (EPI == 2) {
                    ox = 0.5f * ox * (1.f + erff(ox * 0.70710678118654752f));
                    oy = 0.5f * oy * (1.f + erff(oy * 0.70710678118654752f));
                    __nv_bfloat162 hv = __floats2bfloat162_rn(ox, oy);
                    *(__nv_bfloat162*)(Ch + off) = hv;
                } else {
                    float2 o; o.x = ox; o.y = oy;
                    *(float2*)(Cf + off) = o;
                }
            }
        }
    }
}

// ---------------- bf16 mma.sync GEMM (fc2 only: +res epilogue) ------------------
#define PBF 40
#define ASZB (BM*PBF*2)
#define BSZB (BN*PBF*2)
#define STAGEB (ASZB + BSZB)
#define MGEMM16_SMEM (STG * STAGEB)

__device__ __forceinline__ void load_tile16(const __nv_bfloat16* __restrict__ Ag,
                                            const __nv_bfloat16* __restrict__ Bg,
                                            int K, uint32_t sA, uint32_t sB, int t)
{
#pragma unroll
    for (int i = 0; i < 2; i++) {
        int idx = i * 256 + t;
        int row = idx >> 2, ch = idx & 3;
        CP16(sA + row * 80 + ch * 16, Ag + (size_t)row * K + ch * 8);
    }
#pragma unroll
    for (int i = 0; i < 2; i++) {
        int idx = i * 256 + t;
        int row = idx >> 2, ch = idx & 3;
        CP16(sB + row * 80 + ch * 16, Bg + (size_t)row * K + ch * 8);
    }
}

__global__ __launch_bounds__(256)
void mgemm16_k(const __nv_bfloat16* __restrict__ A, const __nv_bfloat16* __restrict__ Bw,
               const float* __restrict__ bias, const float* __restrict__ res,
               float* __restrict__ C, int M, int N, int K)
{
    extern __shared__ char smem[];
    const uint32_t smb = smem_u32(smem);

    const int t = threadIdx.x, lane = t & 31, warp = t >> 5;
    const int wm = warp >> 1, wn = warp & 1;
    const int bm = blockIdx.y * BM, bn = blockIdx.x * BN;
    const int nk = K / BK;
    const int r = lane >> 2, cq = lane & 3;

    float acc[2][8][4];
#pragma unroll
    for (int i = 0; i < 2; i++)
#pragma unroll
        for (int j = 0; j < 8; j++)
#pragma unroll
            for (int q = 0; q < 4; q++) acc[i][j][q] = 0.f;

    const __nv_bfloat16* Abase = A + (size_t)bm * K;
    const __nv_bfloat16* Bbase = Bw + (size_t)bn * K;

#pragma unroll
    for (int s = 0; s < STG - 1; s++) {
        load_tile16(Abase + s * BK, Bbase + s * BK, K,
                    smb + s * STAGEB, smb + s * STAGEB + ASZB, t);
        CP_COMMIT();
    }

    for (int kt = 0; kt < nk; kt++) {
        CP_WAIT1();
        __syncthreads();
        const int pf = kt + STG - 1;
        if (pf < nk) {
            const int st = pf % STG;
            load_tile16(Abase + pf * BK, Bbase + pf * BK, K,
                        smb + st * STAGEB, smb + st * STAGEB + ASZB, t);
        }
        CP_COMMIT();

        const uint32_t* sA = (const uint32_t*)(smem + (kt % STG) * STAGEB);
        const uint32_t* sB = (const uint32_t*)(smem + (kt % STG) * STAGEB + ASZB);
#pragma unroll
        for (int ks = 0; ks < 2; ks++) {
            const int kw = ks * 8;
            uint32_t a[2][4];
#pragma unroll
            for (int mi = 0; mi < 2; mi++) {
                const int row = wm * 32 + mi * 16;
                const int b0 = (row + r) * 20 + kw;
                const int b1 = (row + r + 8) * 20 + kw;
                a[mi][0] = sA[b0 + cq];
                a[mi][1] = sA[b1 + cq];
                a[mi][2] = sA[b0 + 4 + cq];
                a[mi][3] = sA[b1 + 4 + cq];
            }
            uint32_t b[8][2];
#pragma unroll
            for (int ni = 0; ni < 8; ni++) {
                const int col = wn * 64 + ni * 8;
                const int bb = (col + r) * 20 + kw;
                b[ni][0] = sB[bb + cq];
                b[ni][1] = sB[bb + 4 + cq];
            }
#pragma unroll
            for (int mi = 0; mi < 2; mi++)
#pragma unroll
                for (int ni = 0; ni < 8; ni++)
                    mma_bf16(acc[mi][ni], a[mi][0], a[mi][1], a[mi][2], a[mi][3],
                             b[ni][0], b[ni][1]);
        }
    }

#pragma unroll
    for (int ni = 0; ni < 8; ni++) {
        const int col = bn + wn * 64 + ni * 8 + cq * 2;
        const float b0 = bias[col], b1 = bias[col + 1];
#pragma unroll
        for (int mi = 0; mi < 2; mi++) {
            const int row0 = bm + wm * 32 + mi * 16 + r;
#pragma unroll
            for (int h = 0; h < 2; h++) {
                const int row = row0 + h * 8;
                const size_t off = (size_t)row * N + col;
                const float2 rr = *(const float2*)(res + off);
                float2 o;
                o.x = acc[mi][ni][h * 2 + 0] + b0 + rr.x;
                o.y = acc[mi][ni][h * 2 + 1] + b1 + rr.y;
                *(float2*)(C + off) = o;
            }
        }
    }
}

// ---------------- window attention (+ fused residual) ----------------
__global__ __launch_bounds__(256)
void win_attn_k(const float* __restrict__ qkv, const float* __restrict__ rel_table,
                const int* __restrict__ rel_idx, const float* __restrict__ xin,
                float* __restrict__ out)
{
    const int win = blockIdx.x;
    const int h   = blockIdx.y;
    const int b   = win >> 8;
    const int wr  = (win >> 4) & 15;
    const int wc  = win & 15;

    __shared__ float q[64][33], k[64][33], v[64][33];
    __shared__ float s[64][65];

    const int t = threadIdx.x;
#pragma unroll
    for (int i = 0; i < 8; i++) {
        int e = i * 256 + t;
        int tok = e >> 5, d = e & 31;
        int ti = tok >> 3, tj = tok & 7;
        size_t row = ((size_t)(b * 128 + wr * 8 + ti) * 128 + (wc * 8 + tj));
        const float* base = qkv + row * 768 + h * 32 + d;
        q[tok][d] = base[0];
        k[tok][d] = base[256];
        v[tok][d] = base[512];
    }
    __syncthreads();

    const int qi = t >> 2;
    const int j0 = (t & 3) * 16;
#pragma unroll
    for (int j = j0; j < j0 + 16; j++) {
        float a = 0.f;
#pragma unroll
        for (int d = 0; d < 32; d++) a = fmaf(q[qi][d], k[j][d], a);
        s[qi][j] = a * SCALE_ + rel_table[rel_idx[qi * 64 + j] * HEADS + h];
    }
    __syncthreads();

    const int warp = t >> 5, lane = t & 31;
    for (int r = warp * 8; r < warp * 8 + 8; r++) {
        float a = s[r][lane], bvv = s[r][lane + 32];
        float mx = fmaxf(a, bvv);
#pragma unroll
        for (int o = 16; o; o >>= 1) mx = fmaxf(mx, __shfl_xor_sync(0xffffffffu, mx, o));
        a = __expf(a - mx); bvv = __expf(bvv - mx);
        float sum = a + bvv;
#pragma unroll
        for (int o = 16; o; o >>= 1) sum += __shfl_xor_sync(0xffffffffu, sum, o);
        float inv = 1.f / sum;
        s[r][lane] = a * inv; s[r][lane + 32] = bvv * inv;
    }
    __syncthreads();

    const int d0 = (t & 3) * 8;
    float acc[8];
#pragma unroll
    for (int dd = 0; dd < 8; dd++) acc[dd] = 0.f;
    for (int j = 0; j < 64; j++) {
        float p = s[qi][j];
#pragma unroll
        for (int dd = 0; dd < 8; dd++) acc[dd] = fmaf(p, v[j][d0 + dd], acc[dd]);
    }
    int ti = qi >> 3, tj = qi & 7;
    size_t row = ((size_t)(b * 128 + wr * 8 + ti) * 128 + (wc * 8 + tj));
    const float* xr = xin + row * 256 + h * 32 + d0;
    float* ob = out + row * 256 + h * 32 + d0;
#pragma unroll
    for (int dd = 0; dd < 8; dd++) ob[dd] = acc[dd] + xr[dd];
}

// ---------------- LN; RND=1 rounds output to tf32 (GEMM input) ------------------
template<int RND>
__global__ __launch_bounds__(256)
void ln_k(const float* __restrict__ x, const float* __restrict__ w,
          const float* __restrict__ bb, float* __restrict__ lo)
{
    const int warp = threadIdx.x >> 5, lane = threadIdx.x & 31;
    const size_t tok = (size_t)blockIdx.x * 8 + warp;
    const float* xr = x + tok * 256;
    float v[8]; float sum = 0.f;
#pragma unroll
    for (int i = 0; i < 8; i++) { int c = i * 32 + lane; v[i] = xr[c]; sum += v[i]; }
#pragma unroll
    for (int o = 16; o; o >>= 1) sum += __shfl_xor_sync(0xffffffffu, sum, o);
    float mean = sum * (1.f / 256.f);
    float s2 = 0.f;
#pragma unroll
    for (int i = 0; i < 8; i++) { float d = v[i] - mean; s2 += d * d; }
#pragma unroll
    for (int o = 16; o; o >>= 1) s2 += __shfl_xor_sync(0xffffffffu, s2, o);
    float rstd = rsqrtf(s2 * (1.f / 256.f) + 1e-5f);
    float* lr = lo + tok * 256;
#pragma unroll
    for (int i = 0; i < 8; i++) {
        int c = i * 32 + lane;
        float o = (v[i] - mean) * rstd * w[c] + bb[c];
        lr[c] = RND ? rnd_tf32(o) : o;
    }
}

// ---------------- pool + sine pos (tf32-rounded) ----------------
__global__ __launch_bounds__(256)
void pool_pos_k(const float* __restrict__ x, float* __restrict__ out)
{
    const int blk = blockIdx.x;
    const int b  = blk >> 8;
    const int ph = (blk >> 4) & 15;
    const int pw = blk & 15;
    const int c  = threadIdx.x;

    size_t base = ((size_t)(b * 128 + ph * 8) * 128 + pw * 8) * 256 + c;
    float s = 0.f;
#pragma unroll
    for (int i = 0; i < 8; i++)
#pragma unroll
        for (int j = 0; j < 8; j++)
            s += x[base + ((size_t)i * 128 + j) * 256];
    s *= (1.f / 64.f);

    float e; int cc;
    if (c < 128) { e = (float)(ph + 1); cc = c; }
    else         { e = (float)(pw + 1); cc = c - 128; }
    e = e / (16.f + 1e-5f) * 6.283185307179586f;
    float expo = (float)(cc & ~1) / 128.f;
    float tt = powf(10000.f, expo);
    float p = e / tt;
    float pe = (cc & 1) ? cosf(p) : sinf(p);
    out[(size_t)blk * 256 + c] = rnd_tf32(s + pe);
}

// ---------------- global attention ----------------
__global__ __launch_bounds__(256)
void glob_attn_k(const float* __restrict__ qkv, float* __restrict__ out)
{
    const int b = blockIdx.x >> 3;
    const int h = blockIdx.x & 7;
    __shared__ float ks[64][32], vs[64][32];

    const int t = threadIdx.x;
    float q[32];
    const float* qp = qkv + ((size_t)(b * 256 + t)) * 768 + h * 32;
#pragma unroll
    for (int d = 0; d < 32; d++) q[d] = qp[d] * SCALE_;

    float m = -1e30f, l = 0.f, acc[32];
#pragma unroll
    for (int d = 0; d < 32; d++) acc[d] = 0.f;

    for (int c0 = 0; c0 < 256; c0 += 64) {
        __syncthreads();
#pragma unroll
        for (int i = 0; i < 8; i++) {
            int e = i * 256 + t;
            int tk = e >> 5, d = e & 31;
            const float* p = qkv + ((size_t)(b * 256 + c0 + tk)) * 768 + h * 32 + d;
            ks[tk][d] = p[256];
            vs[tk][d] = p[512];
        }
        __syncthreads();
        for (int j = 0; j < 64; j++) {
            float sc = 0.f;
#pragma unroll
            for (int d = 0; d < 32; d++) sc = fmaf(q[d], ks[j][d], sc);
            float mn = fmaxf(m, sc);
            float corr = __expf(m - mn);
            float p = __expf(sc - mn);
            l = l * corr + p;
#pragma unroll
            for (int d = 0; d < 32; d++) acc[d] = acc[d] * corr + p * vs[j][d];
            m = mn;
        }
    }
    float inv = 1.f / l;
    float* op = out + ((size_t)(b * 256 + t)) * 256 + h * 32;
#pragma unroll
    for (int d = 0; d < 32; d++) op[d] = acc[d] * inv;
}

// ---------------- upsample + add + LN (tf32-rounded) ----------------
__global__ __launch_bounds__(256)
void up_add_ln_k(float* __restrict__ x, const float* __restrict__ g,
                 const float* __restrict__ w, const float* __restrict__ bb,
                 float* __restrict__ lo)
{
    const int warp = threadIdx.x >> 5, lane = threadIdx.x & 31;
    const size_t tok = (size_t)blockIdx.x * 8 + warp;
    const int b  = (int)(tok >> 14);
    const int y  = (int)((tok >> 7) & 127);
    const int xx = (int)(tok & 127);

    float sy = (float)y  * (15.f / 127.f);
    float sx = (float)xx * (15.f / 127.f);
    int y0 = (int)floorf(sy); if (y0 > 15) y0 = 15;
    int x0 = (int)floorf(sx); if (x0 > 15) x0 = 15;
    float ty = sy - (float)y0, tx = sx - (float)x0;
    int y1 = min(y0 + 1, 15), x1 = min(x0 + 1, 15);

    const float* g00 = g + ((size_t)((b * 16 + y0) * 16 + x0)) * 256;
    const float* g01 = g + ((size_t)((b * 16 + y0) * 16 + x1)) * 256;
    const float* g10 = g + ((size_t)((b * 16 + y1) * 16 + x0)) * 256;
    const float* g11 = g + ((size_t)((b * 16 + y1) * 16 + x1)) * 256;
    float w00 = (1.f - ty) * (1.f - tx), w01 = (1.f - ty) * tx;
    float w10 = ty * (1.f - tx),         w11 = ty * tx;

    float* xr = x + tok * 256;
    float v[8]; float sum = 0.f;
#pragma unroll
    for (int i = 0; i < 8; i++) {
        int c = i * 32 + lane;
        float up = g00[c] * w00 + g01[c] * w01 + g10[c] * w10 + g11[c] * w11;
        v[i] = xr[c] + up;
        sum += v[i];
    }
#pragma unroll
    for (int o = 16; o; o >>= 1) sum += __shfl_xor_sync(0xffffffffu, sum, o);
    float mean = sum * (1.f / 256.f);
    float s2 = 0.f;
#pragma unroll
    for (int i = 0; i < 8; i++) { float d = v[i] - mean; s2 += d * d; }
#pragma unroll
    for (int o = 16; o; o >>= 1) s2 += __shfl_xor_sync(0xffffffffu, s2, o);
    float rstd = rsqrtf(s2 * (1.f / 256.f) + 1e-5f);
    float* lr = lo + tok * 256;
#pragma unroll
    for (int i = 0; i < 8; i++) {
        int c = i * 32 + lane;
        xr[c] = v[i];
        lr[c] = rnd_tf32((v[i] - mean) * rstd * w[c] + bb[c]);
    }
}

// ---------------- launch ----------------
template<class T>
static T* symaddr(const void* sym)
{
    void* p = nullptr;
    cudaGetSymbolAddress(&p, sym);
    return (T*)p;
}
static void round_arr(const float* in, float* out, int n)
{
    int n4 = n / 4;
    round4_k<<<(n4 + 255) / 256, 256>>>((const float4*)in, (float4*)out, n4);
}

extern "C" void kernel_launch(void* const* d_in, const int* in_sizes, int n_in,
                              void* d_out, int out_size)
{
    const float* x          = (const float*)d_in[0];
    const float* rel_table  = (const float*)d_in[1];
    const float* qkv_w      = (const float*)d_in[2];
    const float* qkv_b      = (const float*)d_in[3];
    const float* qkv2_w     = (const float*)d_in[4];
    const float* qkv2_b     = (const float*)d_in[5];
    const float* proj_ln_w  = (const float*)d_in[6];
    const float* proj_ln_b  = (const float*)d_in[7];
    const float* proj_w     = (const float*)d_in[8];
    const float* proj_b     = (const float*)d_in[9];
    const float* proj2_ln_w = (const float*)d_in[10];
    const float* proj2_ln_b = (const float*)d_in[11];
    const float* proj2_w    = (const float*)d_in[12];
    const float* proj2_b    = (const float*)d_in[13];
    const float* norm1_w    = (const float*)d_in[14];
    const float* norm1_b    = (const float*)d_in[15];
    const float* norm2_w    = (const float*)d_in[16];
    const float* norm2_b    = (const float*)d_in[17];
    const float* fc1_w      = (const float*)d_in[18];
    const float* fc1_b      = (const float*)d_in[19];
    const float* fc2_w      = (const float*)d_in[20];
    const float* fc2_b      = (const float*)d_in[21];
    const int*   rel_idx    = (const int*)  d_in[22];

    float* qkv   = symaddr<float>(g_qkv);
    float* attn  = symaddr<float>(g_attn);
    float* xb    = symaddr<float>(g_x);
    float* ln    = symaddr<float>(g_ln);
    float* pool  = symaddr<float>(g_pool);
    float* qkvg  = symaddr<float>(g_qkvg);
    float* attng = symaddr<float>(g_attng);
    float* wr    = symaddr<float>(g_wr);
    __nv_bfloat16* h16  = symaddr<__nv_bfloat16>(g_h16);
    __nv_bfloat16* wr16 = symaddr<__nv_bfloat16>(g_wr16);

    cudaFuncSetAttribute(mgemm_k<0>, cudaFuncAttributeMaxDynamicSharedMemorySize, MGEMM_SMEM);
    cudaFuncSetAttribute(mgemm_k<1>, cudaFuncAttributeMaxDynamicSharedMemorySize, MGEMM_SMEM);
    cudaFuncSetAttribute(mgemm_k<2>, cudaFuncAttributeMaxDynamicSharedMemorySize, MGEMM_SMEM);
    cudaFuncSetAttribute(mgemm16_k, cudaFuncAttributeMaxDynamicSharedMemorySize, MGEMM16_SMEM);

    const int M = NTOK;

    // 0) pre-round weights: tf32 for qkv/proj/proj2/fc1/qkv2, bf16 for fc2; x -> tf32
    round_arr(qkv_w,   wr + OFF_QKVW,  768 * 256);
    round_arr(proj_w,  wr + OFF_PROJW, 256 * 256);
    round_arr(proj2_w, wr + OFF_PROJ2W,256 * 256);
    round_arr(fc1_w,   wr + OFF_FC1W,  1024 * 256);
    round_arr(qkv2_w,  wr + OFF_QKV2W, 768 * 256);
    round16_k<<<(262144/4 + 255) / 256, 256>>>((const float4*)fc2_w, (uint2*)wr16, 262144/4);
    round_arr(x, attn, M * 256);

    // 1) window-branch QKV (tf32)
    mgemm_k<0><<<dim3(6, M/128), 256, MGEMM_SMEM>>>(attn, wr + OFF_QKVW, qkv_b, nullptr, qkv, M, 768, 256);
    // 2) window attention + fused residual (xb = x + attn)
    win_attn_k<<<dim3(2048, 8), 256>>>(qkv, rel_table, rel_idx, x, xb);
    // 3) ln = LN(xb) (tf32-rounded)
    ln_k<1><<<M/8, 256>>>(xb, proj_ln_w, proj_ln_b, ln);
    // 4) xb += ln @ proj_w^T + proj_b (tf32)
    mgemm_k<1><<<dim3(2, M/128), 256, MGEMM_SMEM>>>(ln, wr + OFF_PROJW, proj_b, xb, xb, M, 256, 256);
    // 5) pool + sine pos
    pool_pos_k<<<2048, 256>>>(xb, pool);
    // 6) global QKV (tf32)
    mgemm_k<0><<<dim3(6, 16), 256, MGEMM_SMEM>>>(pool, wr + OFF_QKV2W, qkv2_b, nullptr, qkvg, 2048, 768, 256);
    // 7) global attention
    glob_attn_k<<<64, 256>>>(qkvg, attng);
    // 8) xb += upsample(attng) ; ln = LN(xb)
    up_add_ln_k<<<M/8, 256>>>(xb, attng, proj2_ln_w, proj2_ln_b, ln);
    // 9) xb += ln @ proj2_w^T + proj2_b (tf32)
    mgemm_k<1><<<dim3(2, M/128), 256, MGEMM_SMEM>>>(ln, wr + OFF_PROJ2W, proj2_b, xb, xb, M, 256, 256);
    // 10) ln = LN(xb, norm1) (tf32-rounded)
    ln_k<1><<<M/8, 256>>>(xb, norm1_w, norm1_b, ln);
    // 11) h16 = gelu(ln @ fc1^T) (tf32 GEMM, bf16 output)
    mgemm_k<2><<<dim3(8, M/128), 256, MGEMM_SMEM>>>(ln, wr + OFF_FC1W, fc1_b, nullptr, h16, M, 1024, 256);
    // 12) xb += h16 @ fc2^T (bf16 GEMM, K=1024)
    mgemm16_k<<<dim3(2, M/128), 256, MGEMM16_SMEM>>>(h16, wr16, fc2_b, xb, xb, M, 256, 1024);
    // 13) out = LN(xb, norm2)
    ln_k<0><<<M/8, 256>>>(xb, norm2_w, norm2_b, (float*)d_out);
}

// round 14
// speedup vs baseline: 1.2543x; 1.1040x over previous
#include <cuda_runtime.h>
#include <cuda_bf16.h>
#include <math.h>
#include <stdint.h>

#define DIM 256
#define HEADS 8
#define WS 8
#define B_ 8
#define NTOK (B_*128*128)          // 131072
#define MLP_HIDDEN 1024
#define SCALE_ 0.17677669529663687f

// ---------------- scratch ----------------
__device__ float g_qkv [NTOK * 768];
__device__ float g_x   [NTOK * DIM];
__device__ float g_ln  [NTOK * DIM];
__device__ __nv_bfloat16 g_xb16[NTOK * DIM];
__device__ __nv_bfloat16 g_lnb [NTOK * DIM];
__device__ __nv_bfloat16 g_h16 [NTOK * MLP_HIDDEN];
__device__ float g_pool [B_ * 256 * DIM];
__device__ float g_qkvg [B_ * 256 * 768];
__device__ float g_attng[B_ * 256 * DIM];
__device__ float g_wr  [327680];              // tf32 weights: proj, proj2, qkv2
__device__ __nv_bfloat16 g_wr16[720896];      // bf16 weights: qkv, fc1, fc2

#define OFFF_PROJW  0
#define OFFF_PROJ2W 65536
#define OFFF_QKV2W  131072
#define OFFB_QKVW   0
#define OFFB_FC1W   196608
#define OFFB_FC2W   458752

// ---------------- helpers ----------------
__device__ __forceinline__ uint32_t smem_u32(const void* p) {
    uint32_t a;
    asm("{ .reg .u64 t; cvta.to.shared.u64 t, %1; cvt.u32.u64 %0, t; }" : "=r"(a) : "l"(p));
    return a;
}
#define CP16(dst, src) \
    asm volatile("cp.async.cg.shared.global [%0], [%1], 16;" :: "r"(dst), "l"(src))
#define CP_COMMIT() asm volatile("cp.async.commit_group;" ::: "memory")
#define CP_WAIT1()  asm volatile("cp.async.wait_group 1;" ::: "memory")

__device__ __forceinline__ uint32_t f2tf32(float f) {
    uint32_t u;
    asm("cvt.rna.tf32.f32 %0, %1;" : "=r"(u) : "f"(f));
    return u;
}
__device__ __forceinline__ float rnd_tf32(float f) {
    return __uint_as_float(f2tf32(f));
}
__device__ __forceinline__ void mma_tf32(float* d, float a0, float a1, float a2, float a3,
                                         float b0, float b1) {
    asm volatile(
        "mma.sync.aligned.m16n8k8.row.col.f32.tf32.tf32.f32 "
        "{%0,%1,%2,%3}, {%4,%5,%6,%7}, {%8,%9}, {%0,%1,%2,%3};"
        : "+f"(d[0]), "+f"(d[1]), "+f"(d[2]), "+f"(d[3])
        : "r"(__float_as_uint(a0)), "r"(__float_as_uint(a1)),
          "r"(__float_as_uint(a2)), "r"(__float_as_uint(a3)),
          "r"(__float_as_uint(b0)), "r"(__float_as_uint(b1)));
}
__device__ __forceinline__ void mma_bf16(float* d, uint32_t a0, uint32_t a1, uint32_t a2,
                                         uint32_t a3, uint32_t b0, uint32_t b1) {
    asm volatile(
        "mma.sync.aligned.m16n8k16.row.col.f32.bf16.bf16.f32 "
        "{%0,%1,%2,%3}, {%4,%5,%6,%7}, {%8,%9}, {%0,%1,%2,%3};"
        : "+f"(d[0]), "+f"(d[1]), "+f"(d[2]), "+f"(d[3])
        : "r"(a0), "r"(a1), "r"(a2), "r"(a3), "r"(b0), "r"(b1));
}

// ---------------- rounding kernels ----------------
__global__ __launch_bounds__(256)
void round4_k(const float4* __restrict__ in, float4* __restrict__ out, int n4)
{
    int i = blockIdx.x * 256 + threadIdx.x;
    if (i < n4) {
        float4 v = in[i];
        v.x = rnd_tf32(v.x); v.y = rnd_tf32(v.y);
        v.z = rnd_tf32(v.z); v.w = rnd_tf32(v.w);
        out[i] = v;
    }
}
__global__ __launch_bounds__(256)
void round16_k(const float4* __restrict__ in, uint2* __restrict__ out, int n4)
{
    int i = blockIdx.x * 256 + threadIdx.x;
    if (i < n4) {
        float4 v = in[i];
        __nv_bfloat162 p0 = __floats2bfloat162_rn(v.x, v.y);
        __nv_bfloat162 p1 = __floats2bfloat162_rn(v.z, v.w);
        uint2 o;
        o.x = *(uint32_t*)&p0;
        o.y = *(uint32_t*)&p1;
        out[i] = o;
    }
}

// ================= tf32 GEMM (proj/proj2/qkv2) ==================================
#define BM 128
#define BN 128
#define BK 32
#define STG 3
#define APAD 36
#define ASZ (BM*APAD)
#define BSZ (BN*APAD)
#define STAGE_F (ASZ + BSZ)
#define MGEMM_SMEM (STG * STAGE_F * 4)

__device__ __forceinline__ void load_tile(const float* __restrict__ Ag,
                                          const float* __restrict__ Bg,
                                          int K, uint32_t sA, uint32_t sB, int t)
{
#pragma unroll
    for (int i = 0; i < 4; i++) {
        int idx = i * 256 + t;
        int row = idx >> 3, ch = idx & 7;
        CP16(sA + row * (APAD * 4) + ch * 16, Ag + (size_t)row * K + ch * 4);
    }
#pragma unroll
    for (int i = 0; i < 4; i++) {
        int idx = i * 256 + t;
        int row = idx >> 3, ch = idx & 7;
        CP16(sB + row * (APAD * 4) + ch * 16, Bg + (size_t)row * K + ch * 4);
    }
}

// EPI: 0 none (fp32), 1 +res (fp32)
template<int EPI>
__global__ __launch_bounds__(256)
void mgemm_k(const float* __restrict__ A, const float* __restrict__ Bw,
             const float* __restrict__ bias, const float* __restrict__ res,
             float* __restrict__ C, int M, int N, int K)
{
    extern __shared__ float sm[];
    const uint32_t smb = smem_u32(sm);

    const int t = threadIdx.x, lane = t & 31, warp = t >> 5;
    const int wm = warp >> 1, wn = warp & 1;
    const int bm = blockIdx.y * BM, bn = blockIdx.x * BN;
    const int nk = K / BK;
    const int r = lane >> 2, cq = lane & 3;

    float acc[2][8][4];
#pragma unroll
    for (int i = 0; i < 2; i++)
#pragma unroll
        for (int j = 0; j < 8; j++)
#pragma unroll
            for (int q = 0; q < 4; q++) acc[i][j][q] = 0.f;

    const float* Abase = A + (size_t)bm * K;
    const float* Bbase = Bw + (size_t)bn * K;

#pragma unroll
    for (int s = 0; s < STG - 1; s++) {
        load_tile(Abase + s * BK, Bbase + s * BK, K,
                  smb + s * STAGE_F * 4, smb + (s * STAGE_F + ASZ) * 4, t);
        CP_COMMIT();
    }

    for (int kt = 0; kt < nk; kt++) {
        CP_WAIT1();
        __syncthreads();
        const int pf = kt + STG - 1;
        if (pf < nk) {
            const int st = pf % STG;
            load_tile(Abase + pf * BK, Bbase + pf * BK, K,
                      smb + st * STAGE_F * 4, smb + (st * STAGE_F + ASZ) * 4, t);
        }
        CP_COMMIT();

        const float* sA = sm + (kt % STG) * STAGE_F;
        const float* sB = sA + ASZ;
#pragma unroll
        for (int ks = 0; ks < 4; ks++) {
            const int k0 = ks * 8;
            float a[2][4];
#pragma unroll
            for (int mi = 0; mi < 2; mi++) {
                const int row = wm * 32 + mi * 16;
                a[mi][0] = sA[(row + r)     * APAD + k0 + cq];
                a[mi][1] = sA[(row + r + 8) * APAD + k0 + cq];
                a[mi][2] = sA[(row + r)     * APAD + k0 + cq + 4];
                a[mi][3] = sA[(row + r + 8) * APAD + k0 + cq + 4];
            }
            float b[8][2];
#pragma unroll
            for (int ni = 0; ni < 8; ni++) {
                const int col = wn * 64 + ni * 8;
                b[ni][0] = sB[(col + r) * APAD + k0 + cq];
                b[ni][1] = sB[(col + r) * APAD + k0 + cq + 4];
            }
#pragma unroll
            for (int mi = 0; mi < 2; mi++)
#pragma unroll
                for (int ni = 0; ni < 8; ni++)
                    mma_tf32(acc[mi][ni], a[mi][0], a[mi][1], a[mi][2], a[mi][3],
                             b[ni][0], b[ni][1]);
        }
    }

#pragma unroll
    for (int ni = 0; ni < 8; ni++) {
        const int col = bn + wn * 64 + ni * 8 + cq * 2;
        const float b0 = bias[col], b1 = bias[col + 1];
#pragma unroll
        for (int mi = 0; mi < 2; mi++) {
            const int row0 = bm + wm * 32 + mi * 16 + r;
#pragma unroll
            for (int h = 0; h < 2; h++) {
                const int row = row0 + h * 8;
                float2 o;
                o.x = acc[mi][ni][h * 2 + 0] + b0;
                o.y = acc[mi][ni][h * 2 + 1] + b1;
                const size_t off = (size_t)row * N + col;
                if (EPI == 1) {
                    const float2 rr = *(const float2*)(res + off);
                    o.x += rr.x; o.y += rr.y;
                }
                *(float2*)(C + off) = o;
            }
        }
    }
}

// ================= bf16 GEMM (qkv / fc1 / fc2) ==================================
#define PBF 40
#define ASZB (BM*PBF*2)
#define BSZB (BN*PBF*2)
#define STAGEB (ASZB + BSZB)
#define MGEMM16_SMEM (STG * STAGEB)

__device__ __forceinline__ void load_tile16(const __nv_bfloat16* __restrict__ Ag,
                                            const __nv_bfloat16* __restrict__ Bg,
                                            int K, uint32_t sA, uint32_t sB, int t)
{
#pragma unroll
    for (int i = 0; i < 2; i++) {
        int idx = i * 256 + t;
        int row = idx >> 2, ch = idx & 3;
        CP16(sA + row * 80 + ch * 16, Ag + (size_t)row * K + ch * 8);
    }
#pragma unroll
    for (int i = 0; i < 2; i++) {
        int idx = i * 256 + t;
        int row = idx >> 2, ch = idx & 3;
        CP16(sB + row * 80 + ch * 16, Bg + (size_t)row * K + ch * 8);
    }
}

// EPI: 0 none (fp32 C), 1 +res (fp32 C), 2 gelu -> bf16 C
template<int EPI>
__global__ __launch_bounds__(256)
void mgemm16_k(const __nv_bfloat16* __restrict__ A, const __nv_bfloat16* __restrict__ Bw,
               const float* __restrict__ bias, const float* __restrict__ res,
               void* __restrict__ Cv, int M, int N, int K)
{
    extern __shared__ char smem[];
    const uint32_t smb = smem_u32(smem);

    const int t = threadIdx.x, lane = t & 31, warp = t >> 5;
    const int wm = warp >> 1, wn = warp & 1;
    const int bm = blockIdx.y * BM, bn = blockIdx.x * BN;
    const int nk = K / BK;
    const int r = lane >> 2, cq = lane & 3;

    float acc[2][8][4];
#pragma unroll
    for (int i = 0; i < 2; i++)
#pragma unroll
        for (int j = 0; j < 8; j++)
#pragma unroll
            for (int q = 0; q < 4; q++) acc[i][j][q] = 0.f;

    const __nv_bfloat16* Abase = A + (size_t)bm * K;
    const __nv_bfloat16* Bbase = Bw + (size_t)bn * K;

#pragma unroll
    for (int s = 0; s < STG - 1; s++) {
        load_tile16(Abase + s * BK, Bbase + s * BK, K,
                    smb + s * STAGEB, smb + s * STAGEB + ASZB, t);
        CP_COMMIT();
    }

    for (int kt = 0; kt < nk; kt++) {
        CP_WAIT1();
        __syncthreads();
        const int pf = kt + STG - 1;
        if (pf < nk) {
            const int st = pf % STG;
            load_tile16(Abase + pf * BK, Bbase + pf * BK, K,
                        smb + st * STAGEB, smb + st * STAGEB + ASZB, t);
        }
        CP_COMMIT();

        const uint32_t* sA = (const uint32_t*)(smem + (kt % STG) * STAGEB);
        const uint32_t* sB = (const uint32_t*)(smem + (kt % STG) * STAGEB + ASZB);
#pragma unroll
        for (int ks = 0; ks < 2; ks++) {
            const int kw = ks * 8;
            uint32_t a[2][4];
#pragma unroll
            for (int mi = 0; mi < 2; mi++) {
                const int row = wm * 32 + mi * 16;
                const int b0 = (row + r) * 20 + kw;
                const int b1 = (row + r + 8) * 20 + kw;
                a[mi][0] = sA[b0 + cq];
                a[mi][1] = sA[b1 + cq];
                a[mi][2] = sA[b0 + 4 + cq];
                a[mi][3] = sA[b1 + 4 + cq];
            }
            uint32_t b[8][2];
#pragma unroll
            for (int ni = 0; ni < 8; ni++) {
                const int col = wn * 64 + ni * 8;
                const int bb = (col + r) * 20 + kw;
                b[ni][0] = sB[bb + cq];
                b[ni][1] = sB[bb + 4 + cq];
            }
#pragma unroll
            for (int mi = 0; mi < 2; mi++)
#pragma unroll
                for (int ni = 0; ni < 8; ni++)
                    mma_bf16(acc[mi][ni], a[mi][0], a[mi][1], a[mi][2], a[mi][3],
                             b[ni][0], b[ni][1]);
        }
    }

    float* Cf = (float*)Cv;
    __nv_bfloat16* Ch = (__nv_bfloat16*)Cv;
#pragma unroll
    for (int ni = 0; ni < 8; ni++) {
        const int col = bn + wn * 64 + ni * 8 + cq * 2;
        const float b0 = bias[col], b1 = bias[col + 1];
#pragma unroll
        for (int mi = 0; mi < 2; mi++) {
            const int row0 = bm + wm * 32 + mi * 16 + r;
#pragma unroll
            for (int h = 0; h < 2; h++) {
                const int row = row0 + h * 8;
                float ox = acc[mi][ni][h * 2 + 0] + b0;
                float oy = acc[mi][ni][h * 2 + 1] + b1;
                const size_t off = (size_t)row * N + col;
                if (EPI == 1) {
                    const float2 rr = *(const float2*)(res + off);
                    ox += rr.x; oy += rr.y;
                }
                if (EPI == 2) {
                    ox = 0.5f * ox * (1.f + erff(ox * 0.70710678118654752f));
                    oy = 0.5f * oy * (1.f + erff(oy * 0.70710678118654752f));
                    __nv_bfloat162 hv = __floats2bfloat162_rn(ox, oy);
                    *(__nv_bfloat162*)(Ch + off) = hv;
                } else {
                    float2 o; o.x = ox; o.y = oy;
                    *(float2*)(Cf + off) = o;
                }
            }
        }
    }
}

// ---------------- window attention (+ fused residual) ----------------
__global__ __launch_bounds__(256)
void win_attn_k(const float* __restrict__ qkv, const float* __restrict__ rel_table,
                const int* __restrict__ rel_idx, const float* __restrict__ xin,
                float* __restrict__ out)
{
    const int win = blockIdx.x;
    const int h   = blockIdx.y;
    const int b   = win >> 8;
    const int wr  = (win >> 4) & 15;
    const int wc  = win & 15;

    __shared__ float q[64][33], k[64][33], v[64][33];
    __shared__ float s[64][65];

    const int t = threadIdx.x;
#pragma unroll
    for (int i = 0; i < 8; i++) {
        int e = i * 256 + t;
        int tok = e >> 5, d = e & 31;
        int ti = tok >> 3, tj = tok & 7;
        size_t row = ((size_t)(b * 128 + wr * 8 + ti) * 128 + (wc * 8 + tj));
        const float* base = qkv + row * 768 + h * 32 + d;
        q[tok][d] = base[0];
        k[tok][d] = base[256];
        v[tok][d] = base[512];
    }
    __syncthreads();

    const int qi = t >> 2;
    const int j0 = (t & 3) * 16;
#pragma unroll
    for (int j = j0; j < j0 + 16; j++) {
        float a = 0.f;
#pragma unroll
        for (int d = 0; d < 32; d++) a = fmaf(q[qi][d], k[j][d], a);
        s[qi][j] = a * SCALE_ + rel_table[rel_idx[qi * 64 + j] * HEADS + h];
    }
    __syncthreads();

    const int warp = t >> 5, lane = t & 31;
    for (int r = warp * 8; r < warp * 8 + 8; r++) {
        float a = s[r][lane], bvv = s[r][lane + 32];
        float mx = fmaxf(a, bvv);
#pragma unroll
        for (int o = 16; o; o >>= 1) mx = fmaxf(mx, __shfl_xor_sync(0xffffffffu, mx, o));
        a = __expf(a - mx); bvv = __expf(bvv - mx);
        float sum = a + bvv;
#pragma unroll
        for (int o = 16; o; o >>= 1) sum += __shfl_xor_sync(0xffffffffu, sum, o);
        float inv = 1.f / sum;
        s[r][lane] = a * inv; s[r][lane + 32] = bvv * inv;
    }
    __syncthreads();

    const int d0 = (t & 3) * 8;
    float acc[8];
#pragma unroll
    for (int dd = 0; dd < 8; dd++) acc[dd] = 0.f;
    for (int j = 0; j < 64; j++) {
        float p = s[qi][j];
#pragma unroll
        for (int dd = 0; dd < 8; dd++) acc[dd] = fmaf(p, v[j][d0 + dd], acc[dd]);
    }
    int ti = qi >> 3, tj = qi & 7;
    size_t row = ((size_t)(b * 128 + wr * 8 + ti) * 128 + (wc * 8 + tj));
    const float* xr = xin + row * 256 + h * 32 + d0;
    float* ob = out + row * 256 + h * 32 + d0;
#pragma unroll
    for (int dd = 0; dd < 8; dd++) ob[dd] = acc[dd] + xr[dd];
}

// ---------------- LN; RND=1 -> tf32 fp32 out ----------------
template<int RND>
__global__ __launch_bounds__(256)
void ln_k(const float* __restrict__ x, const float* __restrict__ w,
          const float* __restrict__ bb, float* __restrict__ lo)
{
    const int warp = threadIdx.x >> 5, lane = threadIdx.x & 31;
    const size_t tok = (size_t)blockIdx.x * 8 + warp;
    const float* xr = x + tok * 256;
    float v[8]; float sum = 0.f;
#pragma unroll
    for (int i = 0; i < 8; i++) { int c = i * 32 + lane; v[i] = xr[c]; sum += v[i]; }
#pragma unroll
    for (int o = 16; o; o >>= 1) sum += __shfl_xor_sync(0xffffffffu, sum, o);
    float mean = sum * (1.f / 256.f);
    float s2 = 0.f;
#pragma unroll
    for (int i = 0; i < 8; i++) { float d = v[i] - mean; s2 += d * d; }
#pragma unroll
    for (int o = 16; o; o >>= 1) s2 += __shfl_xor_sync(0xffffffffu, s2, o);
    float rstd = rsqrtf(s2 * (1.f / 256.f) + 1e-5f);
    float* lr = lo + tok * 256;
#pragma unroll
    for (int i = 0; i < 8; i++) {
        int c = i * 32 + lane;
        float o = (v[i] - mean) * rstd * w[c] + bb[c];
        lr[c] = RND ? rnd_tf32(o) : o;
    }
}

// ---------------- LN -> bf16 out (fc1 input) ----------------
__global__ __launch_bounds__(256)
void ln16_k(const float* __restrict__ x, const float* __restrict__ w,
            const float* __restrict__ bb, __nv_bfloat16* __restrict__ lo)
{
    const int warp = threadIdx.x >> 5, lane = threadIdx.x & 31;
    const size_t tok = (size_t)blockIdx.x * 8 + warp;
    const float* xr = x + tok * 256;
    float v[8]; float sum = 0.f;
#pragma unroll
    for (int i = 0; i < 8; i++) { int c = i * 32 + lane; v[i] = xr[c]; sum += v[i]; }
#pragma unroll
    for (int o = 16; o; o >>= 1) sum += __shfl_xor_sync(0xffffffffu, sum, o);
    float mean = sum * (1.f / 256.f);
    float s2 = 0.f;
#pragma unroll
    for (int i = 0; i < 8; i++) { float d = v[i] - mean; s2 += d * d; }
#pragma unroll
    for (int o = 16; o; o >>= 1) s2 += __shfl_xor_sync(0xffffffffu, s2, o);
    float rstd = rsqrtf(s2 * (1.f / 256.f) + 1e-5f);
    __nv_bfloat16* lr = lo + tok * 256;
#pragma unroll
    for (int i = 0; i < 8; i++) {
        int c = i * 32 + lane;
        lr[c] = __float2bfloat16_rn((v[i] - mean) * rstd * w[c] + bb[c]);
    }
}

// ---------------- pool + sine pos (tf32-rounded) ----------------
__global__ __launch_bounds__(256)
void pool_pos_k(const float* __restrict__ x, float* __restrict__ out)
{
    const int blk = blockIdx.x;
    const int b  = blk >> 8;
    const int ph = (blk >> 4) & 15;
    const int pw = blk & 15;
    const int c  = threadIdx.x;

    size_t base = ((size_t)(b * 128 + ph * 8) * 128 + pw * 8) * 256 + c;
    float s = 0.f;
#pragma unroll
    for (int i = 0; i < 8; i++)
#pragma unroll
        for (int j = 0; j < 8; j++)
            s += x[base + ((size_t)i * 128 + j) * 256];
    s *= (1.f / 64.f);

    float e; int cc;
    if (c < 128) { e = (float)(ph + 1); cc = c; }
    else         { e = (float)(pw + 1); cc = c - 128; }
    e = e / (16.f + 1e-5f) * 6.283185307179586f;
    float expo = (float)(cc & ~1) / 128.f;
    float tt = powf(10000.f, expo);
    float p = e / tt;
    float pe = (cc & 1) ? cosf(p) : sinf(p);
    out[(size_t)blk * 256 + c] = rnd_tf32(s + pe);
}

// ---------------- global attention ----------------
__global__ __launch_bounds__(256)
void glob_attn_k(const float* __restrict__ qkv, float* __restrict__ out)
{
    const int b = blockIdx.x >> 3;
    const int h = blockIdx.x & 7;
    __shared__ float ks[64][32], vs[64][32];

    const int t = threadIdx.x;
    float q[32];
    const float* qp = qkv + ((size_t)(b * 256 + t)) * 768 + h * 32;
#pragma unroll
    for (int d = 0; d < 32; d++) q[d] = qp[d] * SCALE_;

    float m = -1e30f, l = 0.f, acc[32];
#pragma unroll
    for (int d = 0; d < 32; d++) acc[d] = 0.f;

    for (int c0 = 0; c0 < 256; c0 += 64) {
        __syncthreads();
#pragma unroll
        for (int i = 0; i < 8; i++) {
            int e = i * 256 + t;
            int tk = e >> 5, d = e & 31;
            const float* p = qkv + ((size_t)(b * 256 + c0 + tk)) * 768 + h * 32 + d;
            ks[tk][d] = p[256];
            vs[tk][d] = p[512];
        }
        __syncthreads();
        for (int j = 0; j < 64; j++) {
            float sc = 0.f;
#pragma unroll
            for (int d = 0; d < 32; d++) sc = fmaf(q[d], ks[j][d], sc);
            float mn = fmaxf(m, sc);
            float corr = __expf(m - mn);
            float p = __expf(sc - mn);
            l = l * corr + p;
#pragma unroll
            for (int d = 0; d < 32; d++) acc[d] = acc[d] * corr + p * vs[j][d];
            m = mn;
        }
    }
    float inv = 1.f / l;
    float* op = out + ((size_t)(b * 256 + t)) * 256 + h * 32;
#pragma unroll
    for (int d = 0; d < 32; d++) op[d] = acc[d] * inv;
}

// ---------------- upsample + add + LN (tf32-rounded) ----------------
__global__ __launch_bounds__(256)
void up_add_ln_k(float* __restrict__ x, const float* __restrict__ g,
                 const float* __restrict__ w, const float* __restrict__ bb,
                 float* __restrict__ lo)
{
    const int warp = threadIdx.x >> 5, lane = threadIdx.x & 31;
    const size_t tok = (size_t)blockIdx.x * 8 + warp;
    const int b  = (int)(tok >> 14);
    const int y  = (int)((tok >> 7) & 127);
    const int xx = (int)(tok & 127);

    float sy = (float)y  * (15.f / 127.f);
    float sx = (float)xx * (15.f / 127.f);
    int y0 = (int)floorf(sy); if (y0 > 15) y0 = 15;
    int x0 = (int)floorf(sx); if (x0 > 15) x0 = 15;
    float ty = sy - (float)y0, tx = sx - (float)x0;
    int y1 = min(y0 + 1, 15), x1 = min(x0 + 1, 15);

    const float* g00 = g + ((size_t)((b * 16 + y0) * 16 + x0)) * 256;
    const float* g01 = g + ((size_t)((b * 16 + y0) * 16 + x1)) * 256;
    const float* g10 = g + ((size_t)((b * 16 + y1) * 16 + x0)) * 256;
    const float* g11 = g + ((size_t)((b * 16 + y1) * 16 + x1)) * 256;
    float w00 = (1.f - ty) * (1.f - tx), w01 = (1.f - ty) * tx;
    float w10 = ty * (1.f - tx),         w11 = ty * tx;

    float* xr = x + tok * 256;
    float v[8]; float sum = 0.f;
#pragma unroll
    for (int i = 0; i < 8; i++) {
        int c = i * 32 + lane;
        float up = g00[c] * w00 + g01[c] * w01 + g10[c] * w10 + g11[c] * w11;
        v[i] = xr[c] + up;
        sum += v[i];
    }
#pragma unroll
    for (int o = 16; o; o >>= 1) sum += __shfl_xor_sync(0xffffffffu, sum, o);
    float mean = sum * (1.f / 256.f);
    float s2 = 0.f;
#pragma unroll
    for (int i = 0; i < 8; i++) { float d = v[i] - mean; s2 += d * d; }
#pragma unroll
    for (int o = 16; o; o >>= 1) s2 += __shfl_xor_sync(0xffffffffu, s2, o);
    float rstd = rsqrtf(s2 * (1.f / 256.f) + 1e-5f);
    float* lr = lo + tok * 256;
#pragma unroll
    for (int i = 0; i < 8; i++) {
        int c = i * 32 + lane;
        xr[c] = v[i];
        lr[c] = rnd_tf32((v[i] - mean) * rstd * w[c] + bb[c]);
    }
}

// ---------------- launch ----------------
template<class T>
static T* symaddr(const void* sym)
{
    void* p = nullptr;
    cudaGetSymbolAddress(&p, sym);
    return (T*)p;
}
static void round_arr(const float* in, float* out, int n)
{
    int n4 = n / 4;
    round4_k<<<(n4 + 255) / 256, 256>>>((const float4*)in, (float4*)out, n4);
}
static void round_arr16(const float* in, __nv_bfloat16* out, int n)
{
    int n4 = n / 4;
    round16_k<<<(n4 + 255) / 256, 256>>>((const float4*)in, (uint2*)out, n4);
}

extern "C" void kernel_launch(void* const* d_in, const int* in_sizes, int n_in,
                              void* d_out, int out_size)
{
    const float* x          = (const float*)d_in[0];
    const float* rel_table  = (const float*)d_in[1];
    const float* qkv_w      = (const float*)d_in[2];
    const float* qkv_b      = (const float*)d_in[3];
    const float* qkv2_w     = (const float*)d_in[4];
    const float* qkv2_b     = (const float*)d_in[5];
    const float* proj_ln_w  = (const float*)d_in[6];
    const float* proj_ln_b  = (const float*)d_in[7];
    const float* proj_w     = (const float*)d_in[8];
    const float* proj_b     = (const float*)d_in[9];
    const float* proj2_ln_w = (const float*)d_in[10];
    const float* proj2_ln_b = (const float*)d_in[11];
    const float* proj2_w    = (const float*)d_in[12];
    const float* proj2_b    = (const float*)d_in[13];
    const float* norm1_w    = (const float*)d_in[14];
    const float* norm1_b    = (const float*)d_in[15];
    const float* norm2_w    = (const float*)d_in[16];
    const float* norm2_b    = (const float*)d_in[17];
    const float* fc1_w      = (const float*)d_in[18];
    const float* fc1_b      = (const float*)d_in[19];
    const float* fc2_w      = (const float*)d_in[20];
    const float* fc2_b      = (const float*)d_in[21];
    const int*   rel_idx    = (const int*)  d_in[22];

    float* qkv   = symaddr<float>(g_qkv);
    float* xb    = symaddr<float>(g_x);
    float* ln    = symaddr<float>(g_ln);
    float* pool  = symaddr<float>(g_pool);
    float* qkvg  = symaddr<float>(g_qkvg);
    float* attng = symaddr<float>(g_attng);
    float* wr    = symaddr<float>(g_wr);
    __nv_bfloat16* xb16 = symaddr<__nv_bfloat16>(g_xb16);
    __nv_bfloat16* lnb  = symaddr<__nv_bfloat16>(g_lnb);
    __nv_bfloat16* h16  = symaddr<__nv_bfloat16>(g_h16);
    __nv_bfloat16* wr16 = symaddr<__nv_bfloat16>(g_wr16);

    cudaFuncSetAttribute(mgemm_k<0>, cudaFuncAttributeMaxDynamicSharedMemorySize, MGEMM_SMEM);
    cudaFuncSetAttribute(mgemm_k<1>, cudaFuncAttributeMaxDynamicSharedMemorySize, MGEMM_SMEM);
    cudaFuncSetAttribute(mgemm16_k<0>, cudaFuncAttributeMaxDynamicSharedMemorySize, MGEMM16_SMEM);
    cudaFuncSetAttribute(mgemm16_k<1>, cudaFuncAttributeMaxDynamicSharedMemorySize, MGEMM16_SMEM);
    cudaFuncSetAttribute(mgemm16_k<2>, cudaFuncAttributeMaxDynamicSharedMemorySize, MGEMM16_SMEM);

    const int M = NTOK;

    // 0) pre-round weights: bf16 for qkv/fc1/fc2, tf32 for proj/proj2/qkv2; x -> bf16
    round_arr16(qkv_w, wr16 + OFFB_QKVW, 768 * 256);
    round_arr16(fc1_w, wr16 + OFFB_FC1W, 1024 * 256);
    round_arr16(fc2_w, wr16 + OFFB_FC2W, 256 * 1024);
    round_arr(proj_w,  wr + OFFF_PROJW,  256 * 256);
    round_arr(proj2_w, wr + OFFF_PROJ2W, 256 * 256);
    round_arr(qkv2_w,  wr + OFFF_QKV2W,  768 * 256);
    round_arr16(x, xb16, M * 256);

    // 1) window-branch QKV (bf16 GEMM, fp32 out)
    mgemm16_k<0><<<dim3(6, M/128), 256, MGEMM16_SMEM>>>(xb16, wr16 + OFFB_QKVW, qkv_b, nullptr, qkv, M, 768, 256);
    // 2) window attention + fused residual (xb = x + attn)
    win_attn_k<<<dim3(2048, 8), 256>>>(qkv, rel_table, rel_idx, x, xb);
    // 3) ln = LN(xb) (tf32-rounded)
    ln_k<1><<<M/8, 256>>>(xb, proj_ln_w, proj_ln_b, ln);
    // 4) xb += ln @ proj_w^T + proj_b (tf32)
    mgemm_k<1><<<dim3(2, M/128), 256, MGEMM_SMEM>>>(ln, wr + OFFF_PROJW, proj_b, xb, xb, M, 256, 256);
    // 5) pool + sine pos
    pool_pos_k<<<2048, 256>>>(xb, pool);
    // 6) global QKV (tf32)
    mgemm_k<0><<<dim3(6, 16), 256, MGEMM_SMEM>>>(pool, wr + OFFF_QKV2W, qkv2_b, nullptr, qkvg, 2048, 768, 256);
    // 7) global attention
    glob_attn_k<<<64, 256>>>(qkvg, attng);
    // 8) xb += upsample(attng) ; ln = LN(xb)
    up_add_ln_k<<<M/8, 256>>>(xb, attng, proj2_ln_w, proj2_ln_b, ln);
    // 9) xb += ln @ proj2_w^T + proj2_b (tf32)
    mgemm_k<1><<<dim3(2, M/128), 256, MGEMM_SMEM>>>(ln, wr + OFFF_PROJ2W, proj2_b, xb, xb, M, 256, 256);
    // 10) lnb = LN(xb, norm1) -> bf16
    ln16_k<<<M/8, 256>>>(xb, norm1_w, norm1_b, lnb);
    // 11) h16 = gelu(lnb @ fc1^T) (bf16 GEMM, bf16 out)
    mgemm16_k<2><<<dim3(8, M/128), 256, MGEMM16_SMEM>>>(lnb, wr16 + OFFB_FC1W, fc1_b, nullptr, h16, M, 1024, 256);
    // 12) xb += h16 @ fc2^T (bf16 GEMM, K=1024)
    mgemm16_k<1><<<dim3(2, M/128), 256, MGEMM16_SMEM>>>(h16, wr16 + OFFB_FC2W, fc2_b, xb, xb, M, 256, 1024);
    // 13) out = LN(xb, norm2)
    ln_k<0><<<M/8, 256>>>(xb, norm2_w, norm2_b, (float*)d_out);
}

// round 16
// speedup vs baseline: 1.2612x; 1.0055x over previous
#include <cuda_runtime.h>
#include <cuda_bf16.h>
#include <math.h>
#include <stdint.h>

#define DIM 256
#define HEADS 8
#define WS 8
#define B_ 8
#define NTOK (B_*128*128)          // 131072
#define MLP_HIDDEN 1024
#define SCALE_ 0.17677669529663687f

// ---------------- scratch ----------------
__device__ __nv_bfloat16 g_qkv16[NTOK * 768];
__device__ float g_x   [NTOK * DIM];
__device__ float g_ln  [NTOK * DIM];
__device__ __nv_bfloat16 g_xb16[NTOK * DIM];
__device__ __nv_bfloat16 g_lnb [NTOK * DIM];
__device__ __nv_bfloat16 g_h16 [NTOK * MLP_HIDDEN];
__device__ float g_pool [B_ * 256 * DIM];
__device__ float g_qkvg [B_ * 256 * 768];
__device__ float g_attng[B_ * 256 * DIM];
__device__ float g_wr  [327680];              // tf32 weights: proj, proj2, qkv2
__device__ __nv_bfloat16 g_wr16[720896];      // bf16 weights: qkv, fc1, fc2

#define OFFF_PROJW  0
#define OFFF_PROJ2W 65536
#define OFFF_QKV2W  131072
#define OFFB_QKVW   0
#define OFFB_FC1W   196608
#define OFFB_FC2W   458752

// ---------------- helpers ----------------
__device__ __forceinline__ uint32_t smem_u32(const void* p) {
    uint32_t a;
    asm("{ .reg .u64 t; cvta.to.shared.u64 t, %1; cvt.u32.u64 %0, t; }" : "=r"(a) : "l"(p));
    return a;
}
#define CP16(dst, src) \
    asm volatile("cp.async.cg.shared.global [%0], [%1], 16;" :: "r"(dst), "l"(src))
#define CP_COMMIT() asm volatile("cp.async.commit_group;" ::: "memory")
#define CP_WAIT1()  asm volatile("cp.async.wait_group 1;" ::: "memory")

__device__ __forceinline__ uint32_t f2tf32(float f) {
    uint32_t u;
    asm("cvt.rna.tf32.f32 %0, %1;" : "=r"(u) : "f"(f));
    return u;
}
__device__ __forceinline__ float rnd_tf32(float f) {
    return __uint_as_float(f2tf32(f));
}
__device__ __forceinline__ void mma_tf32(float* d, float a0, float a1, float a2, float a3,
                                         float b0, float b1) {
    asm volatile(
        "mma.sync.aligned.m16n8k8.row.col.f32.tf32.tf32.f32 "
        "{%0,%1,%2,%3}, {%4,%5,%6,%7}, {%8,%9}, {%0,%1,%2,%3};"
        : "+f"(d[0]), "+f"(d[1]), "+f"(d[2]), "+f"(d[3])
        : "r"(__float_as_uint(a0)), "r"(__float_as_uint(a1)),
          "r"(__float_as_uint(a2)), "r"(__float_as_uint(a3)),
          "r"(__float_as_uint(b0)), "r"(__float_as_uint(b1)));
}
__device__ __forceinline__ void mma_bf16(float* d, uint32_t a0, uint32_t a1, uint32_t a2,
                                         uint32_t a3, uint32_t b0, uint32_t b1) {
    asm volatile(
        "mma.sync.aligned.m16n8k16.row.col.f32.bf16.bf16.f32 "
        "{%0,%1,%2,%3}, {%4,%5,%6,%7}, {%8,%9}, {%0,%1,%2,%3};"
        : "+f"(d[0]), "+f"(d[1]), "+f"(d[2]), "+f"(d[3])
        : "r"(a0), "r"(a1), "r"(a2), "r"(a3), "r"(b0), "r"(b1));
}

// ---------------- rounding kernels ----------------
__global__ __launch_bounds__(256)
void round4_k(const float4* __restrict__ in, float4* __restrict__ out, int n4)
{
    int i = blockIdx.x * 256 + threadIdx.x;
    if (i < n4) {
        float4 v = in[i];
        v.x = rnd_tf32(v.x); v.y = rnd_tf32(v.y);
        v.z = rnd_tf32(v.z); v.w = rnd_tf32(v.w);
        out[i] = v;
    }
}
__global__ __launch_bounds__(256)
void round16_k(const float4* __restrict__ in, uint2* __restrict__ out, int n4)
{
    int i = blockIdx.x * 256 + threadIdx.x;
    if (i < n4) {
        float4 v = in[i];
        __nv_bfloat162 p0 = __floats2bfloat162_rn(v.x, v.y);
        __nv_bfloat162 p1 = __floats2bfloat162_rn(v.z, v.w);
        uint2 o;
        o.x = *(uint32_t*)&p0;
        o.y = *(uint32_t*)&p1;
        out[i] = o;
    }
}

// ================= tf32 GEMM (proj/proj2/qkv2) ==================================
#define BM 128
#define BN 128
#define BK 32
#define STG 3
#define APAD 36
#define ASZ (BM*APAD)
#define BSZ (BN*APAD)
#define STAGE_F (ASZ + BSZ)
#define MGEMM_SMEM (STG * STAGE_F * 4)

__device__ __forceinline__ void load_tile(const float* __restrict__ Ag,
                                          const float* __restrict__ Bg,
                                          int K, uint32_t sA, uint32_t sB, int t)
{
#pragma unroll
    for (int i = 0; i < 4; i++) {
        int idx = i * 256 + t;
        int row = idx >> 3, ch = idx & 7;
        CP16(sA + row * (APAD * 4) + ch * 16, Ag + (size_t)row * K + ch * 4);
    }
#pragma unroll
    for (int i = 0; i < 4; i++) {
        int idx = i * 256 + t;
        int row = idx >> 3, ch = idx & 7;
        CP16(sB + row * (APAD * 4) + ch * 16, Bg + (size_t)row * K + ch * 4);
    }
}

// EPI: 0 none, 1 +res
template<int EPI>
__global__ __launch_bounds__(256)
void mgemm_k(const float* __restrict__ A, const float* __restrict__ Bw,
             const float* __restrict__ bias, const float* __restrict__ res,
             float* __restrict__ C, int M, int N, int K)
{
    extern __shared__ float sm[];
    const uint32_t smb = smem_u32(sm);

    const int t = threadIdx.x, lane = t & 31, warp = t >> 5;
    const int wm = warp >> 1, wn = warp & 1;
    const int bm = blockIdx.y * BM, bn = blockIdx.x * BN;
    const int nk = K / BK;
    const int r = lane >> 2, cq = lane & 3;

    float acc[2][8][4];
#pragma unroll
    for (int i = 0; i < 2; i++)
#pragma unroll
        for (int j = 0; j < 8; j++)
#pragma unroll
            for (int q = 0; q < 4; q++) acc[i][j][q] = 0.f;

    const float* Abase = A + (size_t)bm * K;
    const float* Bbase = Bw + (size_t)bn * K;

#pragma unroll
    for (int s = 0; s < STG - 1; s++) {
        load_tile(Abase + s * BK, Bbase + s * BK, K,
                  smb + s * STAGE_F * 4, smb + (s * STAGE_F + ASZ) * 4, t);
        CP_COMMIT();
    }

    for (int kt = 0; kt < nk; kt++) {
        CP_WAIT1();
        __syncthreads();
        const int pf = kt + STG - 1;
        if (pf < nk) {
            const int st = pf % STG;
            load_tile(Abase + pf * BK, Bbase + pf * BK, K,
                      smb + st * STAGE_F * 4, smb + (st * STAGE_F + ASZ) * 4, t);
        }
        CP_COMMIT();

        const float* sA = sm + (kt % STG) * STAGE_F;
        const float* sB = sA + ASZ;
#pragma unroll
        for (int ks = 0; ks < 4; ks++) {
            const int k0 = ks * 8;
            float a[2][4];
#pragma unroll
            for (int mi = 0; mi < 2; mi++) {
                const int row = wm * 32 + mi * 16;
                a[mi][0] = sA[(row + r)     * APAD + k0 + cq];
                a[mi][1] = sA[(row + r + 8) * APAD + k0 + cq];
                a[mi][2] = sA[(row + r)     * APAD + k0 + cq + 4];
                a[mi][3] = sA[(row + r + 8) * APAD + k0 + cq + 4];
            }
            float b[8][2];
#pragma unroll
            for (int ni = 0; ni < 8; ni++) {
                const int col = wn * 64 + ni * 8;
                b[ni][0] = sB[(col + r) * APAD + k0 + cq];
                b[ni][1] = sB[(col + r) * APAD + k0 + cq + 4];
            }
#pragma unroll
            for (int mi = 0; mi < 2; mi++)
#pragma unroll
                for (int ni = 0; ni < 8; ni++)
                    mma_tf32(acc[mi][ni], a[mi][0], a[mi][1], a[mi][2], a[mi][3],
                             b[ni][0], b[ni][1]);
        }
    }

#pragma unroll
    for (int ni = 0; ni < 8; ni++) {
        const int col = bn + wn * 64 + ni * 8 + cq * 2;
        const float b0 = bias[col], b1 = bias[col + 1];
#pragma unroll
        for (int mi = 0; mi < 2; mi++) {
            const int row0 = bm + wm * 32 + mi * 16 + r;
#pragma unroll
            for (int h = 0; h < 2; h++) {
                const int row = row0 + h * 8;
                float2 o;
                o.x = acc[mi][ni][h * 2 + 0] + b0;
                o.y = acc[mi][ni][h * 2 + 1] + b1;
                const size_t off = (size_t)row * N + col;
                if (EPI == 1) {
                    const float2 rr = *(const float2*)(res + off);
                    o.x += rr.x; o.y += rr.y;
                }
                *(float2*)(C + off) = o;
            }
        }
    }
}

// ================= bf16 GEMM (qkv / fc1 / fc2) ==================================
#define PBF 40
#define ASZB (BM*PBF*2)
#define BSZB (BN*PBF*2)
#define STAGEB (ASZB + BSZB)
#define MGEMM16_SMEM (STG * STAGEB)

__device__ __forceinline__ void load_tile16(const __nv_bfloat16* __restrict__ Ag,
                                            const __nv_bfloat16* __restrict__ Bg,
                                            int K, uint32_t sA, uint32_t sB, int t)
{
#pragma unroll
    for (int i = 0; i < 2; i++) {
        int idx = i * 256 + t;
        int row = idx >> 2, ch = idx & 3;
        CP16(sA + row * 80 + ch * 16, Ag + (size_t)row * K + ch * 8);
    }
#pragma unroll
    for (int i = 0; i < 2; i++) {
        int idx = i * 256 + t;
        int row = idx >> 2, ch = idx & 3;
        CP16(sB + row * 80 + ch * 16, Bg + (size_t)row * K + ch * 8);
    }
}

// EPI: 0 none (fp32 C), 1 +res (fp32 C), 2 gelu -> bf16 C, 3 plain -> bf16 C
template<int EPI>
__global__ __launch_bounds__(256)
void mgemm16_k(const __nv_bfloat16* __restrict__ A, const __nv_bfloat16* __restrict__ Bw,
               const float* __restrict__ bias, const float* __restrict__ res,
               void* __restrict__ Cv, int M, int N, int K)
{
    extern __shared__ char smem[];
    const uint32_t smb = smem_u32(smem);

    const int t = threadIdx.x, lane = t & 31, warp = t >> 5;
    const int wm = warp >> 1, wn = warp & 1;
    const int bm = blockIdx.y * BM, bn = blockIdx.x * BN;
    const int nk = K / BK;
    const int r = lane >> 2, cq = lane & 3;

    float acc[2][8][4];
#pragma unroll
    for (int i = 0; i < 2; i++)
#pragma unroll
        for (int j = 0; j < 8; j++)
#pragma unroll
            for (int q = 0; q < 4; q++) acc[i][j][q] = 0.f;

    const __nv_bfloat16* Abase = A + (size_t)bm * K;
    const __nv_bfloat16* Bbase = Bw + (size_t)bn * K;

#pragma unroll
    for (int s = 0; s < STG - 1; s++) {
        load_tile16(Abase + s * BK, Bbase + s * BK, K,
                    smb + s * STAGEB, smb + s * STAGEB + ASZB, t);
        CP_COMMIT();
    }

    for (int kt = 0; kt < nk; kt++) {
        CP_WAIT1();
        __syncthreads();
        const int pf = kt + STG - 1;
        if (pf < nk) {
            const int st = pf % STG;
            load_tile16(Abase + pf * BK, Bbase + pf * BK, K,
                        smb + st * STAGEB, smb + st * STAGEB + ASZB, t);
        }
        CP_COMMIT();

        const uint32_t* sA = (const uint32_t*)(smem + (kt % STG) * STAGEB);
        const uint32_t* sB = (const uint32_t*)(smem + (kt % STG) * STAGEB + ASZB);
#pragma unroll
        for (int ks = 0; ks < 2; ks++) {
            const int kw = ks * 8;
            uint32_t a[2][4];
#pragma unroll
            for (int mi = 0; mi < 2; mi++) {
                const int row = wm * 32 + mi * 16;
                const int b0 = (row + r) * 20 + kw;
                const int b1 = (row + r + 8) * 20 + kw;
                a[mi][0] = sA[b0 + cq];
                a[mi][1] = sA[b1 + cq];
                a[mi][2] = sA[b0 + 4 + cq];
                a[mi][3] = sA[b1 + 4 + cq];
            }
            uint32_t b[8][2];
#pragma unroll
            for (int ni = 0; ni < 8; ni++) {
                const int col = wn * 64 + ni * 8;
                const int bb = (col + r) * 20 + kw;
                b[ni][0] = sB[bb + cq];
                b[ni][1] = sB[bb + 4 + cq];
            }
#pragma unroll
            for (int mi = 0; mi < 2; mi++)
#pragma unroll
                for (int ni = 0; ni < 8; ni++)
                    mma_bf16(acc[mi][ni], a[mi][0], a[mi][1], a[mi][2], a[mi][3],
                             b[ni][0], b[ni][1]);
        }
    }

    float* Cf = (float*)Cv;
    __nv_bfloat16* Ch = (__nv_bfloat16*)Cv;
#pragma unroll
    for (int ni = 0; ni < 8; ni++) {
        const int col = bn + wn * 64 + ni * 8 + cq * 2;
        const float b0 = bias[col], b1 = bias[col + 1];
#pragma unroll
        for (int mi = 0; mi < 2; mi++) {
            const int row0 = bm + wm * 32 + mi * 16 + r;
#pragma unroll
            for (int h = 0; h < 2; h++) {
                const int row = row0 + h * 8;
                float ox = acc[mi][ni][h * 2 + 0] + b0;
                float oy = acc[mi][ni][h * 2 + 1] + b1;
                const size_t off = (size_t)row * N + col;
                if (EPI == 1) {
                    const float2 rr = *(const float2*)(res + off);
                    ox += rr.x; oy += rr.y;
                    float2 o; o.x = ox; o.y = oy;
                    *(float2*)(Cf + off) = o;
                } else if (EPI == 2) {
                    ox = 0.5f * ox * (1.f + erff(ox * 0.70710678118654752f));
                    oy = 0.5f * oy * (1.f + erff(oy * 0.70710678118654752f));
                    __nv_bfloat162 hv = __floats2bfloat162_rn(ox, oy);
                    *(__nv_bfloat162*)(Ch + off) = hv;
                } else if (EPI == 3) {
                    __nv_bfloat162 hv = __floats2bfloat162_rn(ox, oy);
                    *(__nv_bfloat162*)(Ch + off) = hv;
                } else {
                    float2 o; o.x = ox; o.y = oy;
                    *(float2*)(Cf + off) = o;
                }
            }
        }
    }
}

// ---------------- window attention (bf16 qkv input, fused residual) -------------
__global__ __launch_bounds__(256)
void win_attn_k(const __nv_bfloat16* __restrict__ qkv, const float* __restrict__ rel_table,
                const int* __restrict__ rel_idx, const float* __restrict__ xin,
                float* __restrict__ out)
{
    const int win = blockIdx.x;
    const int h   = blockIdx.y;
    const int b   = win >> 8;
    const int wr  = (win >> 4) & 15;
    const int wc  = win & 15;

    __shared__ float q[64][33], k[64][33], v[64][33];
    __shared__ float s[64][65];

    const int t = threadIdx.x;
#pragma unroll
    for (int i = 0; i < 8; i++) {
        int e = i * 256 + t;
        int tok = e >> 5, d = e & 31;
        int ti = tok >> 3, tj = tok & 7;
        size_t row = ((size_t)(b * 128 + wr * 8 + ti) * 128 + (wc * 8 + tj));
        const __nv_bfloat16* base = qkv + row * 768 + h * 32 + d;
        q[tok][d] = __bfloat162float(base[0]);
        k[tok][d] = __bfloat162float(base[256]);
        v[tok][d] = __bfloat162float(base[512]);
    }
    __syncthreads();

    const int qi = t >> 2;
    const int j0 = (t & 3) * 16;
#pragma unroll
    for (int j = j0; j < j0 + 16; j++) {
        float a = 0.f;
#pragma unroll
        for (int d = 0; d < 32; d++) a = fmaf(q[qi][d], k[j][d], a);
        s[qi][j] = a * SCALE_ + rel_table[rel_idx[qi * 64 + j] * HEADS + h];
    }
    __syncthreads();

    const int warp = t >> 5, lane = t & 31;
    for (int r = warp * 8; r < warp * 8 + 8; r++) {
        float a = s[r][lane], bvv = s[r][lane + 32];
        float mx = fmaxf(a, bvv);
#pragma unroll
        for (int o = 16; o; o >>= 1) mx = fmaxf(mx, __shfl_xor_sync(0xffffffffu, mx, o));
        a = __expf(a - mx); bvv = __expf(bvv - mx);
        float sum = a + bvv;
#pragma unroll
        for (int o = 16; o; o >>= 1) sum += __shfl_xor_sync(0xffffffffu, sum, o);
        float inv = 1.f / sum;
        s[r][lane] = a * inv; s[r][lane + 32] = bvv * inv;
    }
    __syncthreads();

    const int d0 = (t & 3) * 8;
    float acc[8];
#pragma unroll
    for (int dd = 0; dd < 8; dd++) acc[dd] = 0.f;
    for (int j = 0; j < 64; j++) {
        float p = s[qi][j];
#pragma unroll
        for (int dd = 0; dd < 8; dd++) acc[dd] = fmaf(p, v[j][d0 + dd], acc[dd]);
    }
    int ti = qi >> 3, tj = qi & 7;
    size_t row = ((size_t)(b * 128 + wr * 8 + ti) * 128 + (wc * 8 + tj));
    const float* xr = xin + row * 256 + h * 32 + d0;
    float* ob = out + row * 256 + h * 32 + d0;
#pragma unroll
    for (int dd = 0; dd < 8; dd++) ob[dd] = acc[dd] + xr[dd];
}

// ---------------- LN; RND=1 -> tf32 fp32 out ----------------
template<int RND>
__global__ __launch_bounds__(256)
void ln_k(const float* __restrict__ x, const float* __restrict__ w,
          const float* __restrict__ bb, float* __restrict__ lo)
{
    const int warp = threadIdx.x >> 5, lane = threadIdx.x & 31;
    const size_t tok = (size_t)blockIdx.x * 8 + warp;
    const float* xr = x + tok * 256;
    float v[8]; float sum = 0.f;
#pragma unroll
    for (int i = 0; i < 8; i++) { int c = i * 32 + lane; v[i] = xr[c]; sum += v[i]; }
#pragma unroll
    for (int o = 16; o; o >>= 1) sum += __shfl_xor_sync(0xffffffffu, sum, o);
    float mean = sum * (1.f / 256.f);
    float s2 = 0.f;
#pragma unroll
    for (int i = 0; i < 8; i++) { float d = v[i] - mean; s2 += d * d; }
#pragma unroll
    for (int o = 16; o; o >>= 1) s2 += __shfl_xor_sync(0xffffffffu, s2, o);
    float rstd = rsqrtf(s2 * (1.f / 256.f) + 1e-5f);
    float* lr = lo + tok * 256;
#pragma unroll
    for (int i = 0; i < 8; i++) {
        int c = i * 32 + lane;
        float o = (v[i] - mean) * rstd * w[c] + bb[c];
        lr[c] = RND ? rnd_tf32(o) : o;
    }
}

// ---------------- LN -> bf16 out (fc1 input) ----------------
__global__ __launch_bounds__(256)
void ln16_k(const float* __restrict__ x, const float* __restrict__ w,
            const float* __restrict__ bb, __nv_bfloat16* __restrict__ lo)
{
    const int warp = threadIdx.x >> 5, lane = threadIdx.x & 31;
    const size_t tok = (size_t)blockIdx.x * 8 + warp;
    const float* xr = x + tok * 256;
    float v[8]; float sum = 0.f;
#pragma unroll
    for (int i = 0; i < 8; i++) { int c = i * 32 + lane; v[i] = xr[c]; sum += v[i]; }
#pragma unroll
    for (int o = 16; o; o >>= 1) sum += __shfl_xor_sync(0xffffffffu, sum, o);
    float mean = sum * (1.f / 256.f);
    float s2 = 0.f;
#pragma unroll
    for (int i = 0; i < 8; i++) { float d = v[i] - mean; s2 += d * d; }
#pragma unroll
    for (int o = 16; o; o >>= 1) s2 += __shfl_xor_sync(0xffffffffu, s2, o);
    float rstd = rsqrtf(s2 * (1.f / 256.f) + 1e-5f);
    __nv_bfloat16* lr = lo + tok * 256;
#pragma unroll
    for (int i = 0; i < 8; i++) {
        int c = i * 32 + lane;
        lr[c] = __float2bfloat16_rn((v[i] - mean) * rstd * w[c] + bb[c]);
    }
}

// ---------------- pool + sine pos (tf32-rounded) ----------------
__global__ __launch_bounds__(256)
void pool_pos_k(const float* __restrict__ x, float* __restrict__ out)
{
    const int blk = blockIdx.x;
    const int b  = blk >> 8;
    const int ph = (blk >> 4) & 15;
    const int pw = blk & 15;
    const int c  = threadIdx.x;

    size_t base = ((size_t)(b * 128 + ph * 8) * 128 + pw * 8) * 256 + c;
    float s = 0.f;
#pragma unroll
    for (int i = 0; i < 8; i++)
#pragma unroll
        for (int j = 0; j < 8; j++)
            s += x[base + ((size_t)i * 128 + j) * 256];
    s *= (1.f / 64.f);

    float e; int cc;
    if (c < 128) { e = (float)(ph + 1); cc = c; }
    else         { e = (float)(pw + 1); cc = c - 128; }
    e = e / (16.f + 1e-5f) * 6.283185307179586f;
    float expo = (float)(cc & ~1) / 128.f;
    float tt = powf(10000.f, expo);
    float p = e / tt;
    float pe = (cc & 1) ? cosf(p) : sinf(p);
    out[(size_t)blk * 256 + c] = rnd_tf32(s + pe);
}

// ---------------- global attention ----------------
__global__ __launch_bounds__(256)
void glob_attn_k(const float* __restrict__ qkv, float* __restrict__ out)
{
    const int b = blockIdx.x >> 3;
    const int h = blockIdx.x & 7;
    __shared__ float ks[64][32], vs[64][32];

    const int t = threadIdx.x;
    float q[32];
    const float* qp = qkv + ((size_t)(b * 256 + t)) * 768 + h * 32;
#pragma unroll
    for (int d = 0; d < 32; d++) q[d] = qp[d] * SCALE_;

    float m = -1e30f, l = 0.f, acc[32];
#pragma unroll
    for (int d = 0; d < 32; d++) acc[d] = 0.f;

    for (int c0 = 0; c0 < 256; c0 += 64) {
        __syncthreads();
#pragma unroll
        for (int i = 0; i < 8; i++) {
            int e = i * 256 + t;
            int tk = e >> 5, d = e & 31;
            const float* p = qkv + ((size_t)(b * 256 + c0 + tk)) * 768 + h * 32 + d;
            ks[tk][d] = p[256];
            vs[tk][d] = p[512];
        }
        __syncthreads();
        for (int j = 0; j < 64; j++) {
            float sc = 0.f;
#pragma unroll
            for (int d = 0; d < 32; d++) sc = fmaf(q[d], ks[j][d], sc);
            float mn = fmaxf(m, sc);
            float corr = __expf(m - mn);
            float p = __expf(sc - mn);
            l = l * corr + p;
#pragma unroll
            for (int d = 0; d < 32; d++) acc[d] = acc[d] * corr + p * vs[j][d];
            m = mn;
        }
    }
    float inv = 1.f / l;
    float* op = out + ((size_t)(b * 256 + t)) * 256 + h * 32;
#pragma unroll
    for (int d = 0; d < 32; d++) op[d] = acc[d] * inv;
}

// ---------------- upsample + add + LN (tf32-rounded) ----------------
__global__ __launch_bounds__(256)
void up_add_ln_k(float* __restrict__ x, const float* __restrict__ g,
                 const float* __restrict__ w, const float* __restrict__ bb,
                 float* __restrict__ lo)
{
    const int warp = threadIdx.x >> 5, lane = threadIdx.x & 31;
    const size_t tok = (size_t)blockIdx.x * 8 + warp;
    const int b  = (int)(tok >> 14);
    const int y  = (int)((tok >> 7) & 127);
    const int xx = (int)(tok & 127);

    float sy = (float)y  * (15.f / 127.f);
    float sx = (float)xx * (15.f / 127.f);
    int y0 = (int)floorf(sy); if (y0 > 15) y0 = 15;
    int x0 = (int)floorf(sx); if (x0 > 15) x0 = 15;
    float ty = sy - (float)y0, tx = sx - (float)x0;
    int y1 = min(y0 + 1, 15), x1 = min(x0 + 1, 15);

    const float* g00 = g + ((size_t)((b * 16 + y0) * 16 + x0)) * 256;
    const float* g01 = g + ((size_t)((b * 16 + y0) * 16 + x1)) * 256;
    const float* g10 = g + ((size_t)((b * 16 + y1) * 16 + x0)) * 256;
    const float* g11 = g + ((size_t)((b * 16 + y1) * 16 + x1)) * 256;
    float w00 = (1.f - ty) * (1.f - tx), w01 = (1.f - ty) * tx;
    float w10 = ty * (1.f - tx),         w11 = ty * tx;

    float* xr = x + tok * 256;
    float v[8]; float sum = 0.f;
#pragma unroll
    for (int i = 0; i < 8; i++) {
        int c = i * 32 + lane;
        float up = g00[c] * w00 + g01[c] * w01 + g10[c] * w10 + g11[c] * w11;
        v[i] = xr[c] + up;
        sum += v[i];
    }
#pragma unroll
    for (int o = 16; o; o >>= 1) sum += __shfl_xor_sync(0xffffffffu, sum, o);
    float mean = sum * (1.f / 256.f);
    float s2 = 0.f;
#pragma unroll
    for (int i = 0; i < 8; i++) { float d = v[i] - mean; s2 += d * d; }
#pragma unroll
    for (int o = 16; o; o >>= 1) s2 += __shfl_xor_sync(0xffffffffu, s2, o);
    float rstd = rsqrtf(s2 * (1.f / 256.f) + 1e-5f);
    float* lr = lo + tok * 256;
#pragma unroll
    for (int i = 0; i < 8; i++) {
        int c = i * 32 + lane;
        xr[c] = v[i];
        lr[c] = rnd_tf32((v[i] - mean) * rstd * w[c] + bb[c]);
    }
}

// ---------------- launch ----------------
template<class T>
static T* symaddr(const void* sym)
{
    void* p = nullptr;
    cudaGetSymbolAddress(&p, sym);
    return (T*)p;
}
static void round_arr(const float* in, float* out, int n)
{
    int n4 = n / 4;
    round4_k<<<(n4 + 255) / 256, 256>>>((const float4*)in, (float4*)out, n4);
}
static void round_arr16(const float* in, __nv_bfloat16* out, int n)
{
    int n4 = n / 4;
    round16_k<<<(n4 + 255) / 256, 256>>>((const float4*)in, (uint2*)out, n4);
}

extern "C" void kernel_launch(void* const* d_in, const int* in_sizes, int n_in,
                              void* d_out, int out_size)
{
    const float* x          = (const float*)d_in[0];
    const float* rel_table  = (const float*)d_in[1];
    const float* qkv_w      = (const float*)d_in[2];
    const float* qkv_b      = (const float*)d_in[3];
    const float* qkv2_w     = (const float*)d_in[4];
    const float* qkv2_b     = (const float*)d_in[5];
    const float* proj_ln_w  = (const float*)d_in[6];
    const float* proj_ln_b  = (const float*)d_in[7];
    const float* proj_w     = (const float*)d_in[8];
    const float* proj_b     = (const float*)d_in[9];
    const float* proj2_ln_w = (const float*)d_in[10];
    const float* proj2_ln_b = (const float*)d_in[11];
    const float* proj2_w    = (const float*)d_in[12];
    const float* proj2_b    = (const float*)d_in[13];
    const float* norm1_w    = (const float*)d_in[14];
    const float* norm1_b    = (const float*)d_in[15];
    const float* norm2_w    = (const float*)d_in[16];
    const float* norm2_b    = (const float*)d_in[17];
    const float* fc1_w      = (const float*)d_in[18];
    const float* fc1_b      = (const float*)d_in[19];
    const float* fc2_w      = (const float*)d_in[20];
    const float* fc2_b      = (const float*)d_in[21];
    const int*   rel_idx    = (const int*)  d_in[22];

    float* xb    = symaddr<float>(g_x);
    float* ln    = symaddr<float>(g_ln);
    float* pool  = symaddr<float>(g_pool);
    float* qkvg  = symaddr<float>(g_qkvg);
    float* attng = symaddr<float>(g_attng);
    float* wr    = symaddr<float>(g_wr);
    __nv_bfloat16* qkv16 = symaddr<__nv_bfloat16>(g_qkv16);
    __nv_bfloat16* xb16  = symaddr<__nv_bfloat16>(g_xb16);
    __nv_bfloat16* lnb   = symaddr<__nv_bfloat16>(g_lnb);
    __nv_bfloat16* h16   = symaddr<__nv_bfloat16>(g_h16);
    __nv_bfloat16* wr16  = symaddr<__nv_bfloat16>(g_wr16);

    cudaFuncSetAttribute(mgemm_k<0>, cudaFuncAttributeMaxDynamicSharedMemorySize, MGEMM_SMEM);
    cudaFuncSetAttribute(mgemm_k<1>, cudaFuncAttributeMaxDynamicSharedMemorySize, MGEMM_SMEM);
    cudaFuncSetAttribute(mgemm16_k<1>, cudaFuncAttributeMaxDynamicSharedMemorySize, MGEMM16_SMEM);
    cudaFuncSetAttribute(mgemm16_k<2>, cudaFuncAttributeMaxDynamicSharedMemorySize, MGEMM16_SMEM);
    cudaFuncSetAttribute(mgemm16_k<3>, cudaFuncAttributeMaxDynamicSharedMemorySize, MGEMM16_SMEM);

    const int M = NTOK;

    // 0) pre-round weights (R14 split: bf16 qkv/fc1/fc2, tf32 proj/proj2/qkv2); x -> bf16
    round_arr16(qkv_w, wr16 + OFFB_QKVW, 768 * 256);
    round_arr16(fc1_w, wr16 + OFFB_FC1W, 1024 * 256);
    round_arr16(fc2_w, wr16 + OFFB_FC2W, 256 * 1024);
    round_arr(proj_w,  wr + OFFF_PROJW,  256 * 256);
    round_arr(proj2_w, wr + OFFF_PROJ2W, 256 * 256);
    round_arr(qkv2_w,  wr + OFFF_QKV2W,  768 * 256);
    round_arr16(x, xb16, M * 256);

    // 1) window-branch QKV (bf16 GEMM, bf16 out -> halves qkv traffic)
    mgemm16_k<3><<<dim3(6, M/128), 256, MGEMM16_SMEM>>>(xb16, wr16 + OFFB_QKVW, qkv_b, nullptr, qkv16, M, 768, 256);
    // 2) window attention (bf16 qkv) + fused residual (xb = x + attn)
    win_attn_k<<<dim3(2048, 8), 256>>>(qkv16, rel_table, rel_idx, x, xb);
    // 3) ln = LN(xb) (tf32-rounded)
    ln_k<1><<<M/8, 256>>>(xb, proj_ln_w, proj_ln_b, ln);
    // 4) xb += ln @ proj_w^T + proj_b (tf32)
    mgemm_k<1><<<dim3(2, M/128), 256, MGEMM_SMEM>>>(ln, wr + OFFF_PROJW, proj_b, xb, xb, M, 256, 256);
    // 5) pool + sine pos
    pool_pos_k<<<2048, 256>>>(xb, pool);
    // 6) global QKV (tf32)
    mgemm_k<0><<<dim3(6, 16), 256, MGEMM_SMEM>>>(pool, wr + OFFF_QKV2W, qkv2_b, nullptr, qkvg, 2048, 768, 256);
    // 7) global attention
    glob_attn_k<<<64, 256>>>(qkvg, attng);
    // 8) xb += upsample(attng) ; ln = LN(xb) (tf32-rounded)
    up_add_ln_k<<<M/8, 256>>>(xb, attng, proj2_ln_w, proj2_ln_b, ln);
    // 9) xb += ln @ proj2_w^T + proj2_b (tf32)
    mgemm_k<1><<<dim3(2, M/128), 256, MGEMM_SMEM>>>(ln, wr + OFFF_PROJ2W, proj2_b, xb, xb, M, 256, 256);
    // 10) lnb = LN(xb, norm1) -> bf16
    ln16_k<<<M/8, 256>>>(xb, norm1_w, norm1_b, lnb);
    // 11) h16 = gelu(lnb @ fc1^T) (bf16)
    mgemm16_k<2><<<dim3(8, M/128), 256, MGEMM16_SMEM>>>(lnb, wr16 + OFFB_FC1W, fc1_b, nullptr, h16, M, 1024, 256);
    // 12) xb += h16 @ fc2^T (bf16, K=1024)
    mgemm16_k<1><<<dim3(2, M/128), 256, MGEMM16_SMEM>>>(h16, wr16 + OFFB_FC2W, fc2_b, xb, xb, M, 256, 1024);
    // 13) out = LN(xb, norm2)
    ln_k<0><<<M/8, 256>>>(xb, norm2_w, norm2_b, (float*)d_out);
}